// round 1
// baseline (speedup 1.0000x reference)
#include <cuda_runtime.h>
#include <math.h>

// ---------------------------------------------------------------------------
// PTransformerBlock: S=2048 B=4 D=1024 H=16 K=64 FF=4096, fp32 baseline.
//   q,k,v = x @ W{q,k,v}^T            (layout [S,B,D] rows = (s*B+b))
//   per head n=b*H+h: flash-attn over q_n,k_n,v_n (stride: s->4096, base n*64)
//   t = LN1(x + u @ Wc^T)
//   out = LN2(t + relu(t@W1^T+b1)@W2^T+b2)
// ---------------------------------------------------------------------------

#define SEQ   2048
#define BATCH 4
#define DMODEL 1024
#define NH    64            // B*H
#define HK    64            // head dim
#define FFDIM 4096
#define MROWS (SEQ*BATCH)   // 8192
#define LN_EPS 1e-5f

// scratch (allocation-free: device globals)
__device__ float g_q[MROWS * DMODEL];
__device__ float g_k[MROWS * DMODEL];
__device__ float g_v[MROWS * DMODEL];
__device__ float g_u[MROWS * DMODEL];
__device__ float g_hid[MROWS * FFDIM];

// ---------------------------------------------------------------------------
// Tiled SGEMM: C[M,N] = A[M,Kd] * W[N,Kd]^T  (+ epilogue)
// 128x128 block tile, BK=16, 256 threads, 8x8 microtile.
// EPI: 0=none  1=+bias,relu  2=+bias,+res  3=+res
// Shapes assumed multiples of 128 (M) / 128 (N) / 16 (Kd) -- true here.
// ---------------------------------------------------------------------------
__global__ __launch_bounds__(256) void sgemm128(
    const float* __restrict__ A, const float* __restrict__ W,
    const float* __restrict__ bias, const float* __restrict__ res,
    float* __restrict__ C, int N, int Kd, int EPI)
{
    __shared__ float As[16][128];
    __shared__ float Bs[16][128];

    const int m0 = blockIdx.y * 128;
    const int n0 = blockIdx.x * 128;
    const int tid = threadIdx.x;
    const int tx = tid & 15;        // n-group
    const int ty = tid >> 4;        // m-group

    float acc[8][8];
#pragma unroll
    for (int i = 0; i < 8; i++)
#pragma unroll
        for (int j = 0; j < 8; j++) acc[i][j] = 0.f;

    for (int k0 = 0; k0 < Kd; k0 += 16) {
#pragma unroll
        for (int it = 0; it < 2; it++) {
            int lin = tid + it * 256;       // 0..511 float4 slots
            int row = lin >> 2;             // 0..127
            int c4  = (lin & 3) * 4;        // 0,4,8,12
            float4 va = *(const float4*)(A + (size_t)(m0 + row) * Kd + k0 + c4);
            As[c4 + 0][row] = va.x; As[c4 + 1][row] = va.y;
            As[c4 + 2][row] = va.z; As[c4 + 3][row] = va.w;
            float4 vb = *(const float4*)(W + (size_t)(n0 + row) * Kd + k0 + c4);
            Bs[c4 + 0][row] = vb.x; Bs[c4 + 1][row] = vb.y;
            Bs[c4 + 2][row] = vb.z; Bs[c4 + 3][row] = vb.w;
        }
        __syncthreads();

#pragma unroll
        for (int kk = 0; kk < 16; kk++) {
            float a[8], b[8];
#pragma unroll
            for (int i = 0; i < 8; i++) a[i] = As[kk][ty * 8 + i];
#pragma unroll
            for (int j = 0; j < 8; j++) b[j] = Bs[kk][tx * 8 + j];
#pragma unroll
            for (int i = 0; i < 8; i++)
#pragma unroll
                for (int j = 0; j < 8; j++) acc[i][j] = fmaf(a[i], b[j], acc[i][j]);
        }
        __syncthreads();
    }

#pragma unroll
    for (int i = 0; i < 8; i++) {
        int m = m0 + ty * 8 + i;
#pragma unroll
        for (int j = 0; j < 8; j++) {
            int n = n0 + tx * 8 + j;
            float c = acc[i][j];
            if (EPI == 1)      { c += bias[n]; c = fmaxf(c, 0.f); }
            else if (EPI == 2) { c += bias[n] + res[(size_t)m * N + n]; }
            else if (EPI == 3) { c += res[(size_t)m * N + n]; }
            C[(size_t)m * N + n] = c;
        }
    }
}

// ---------------------------------------------------------------------------
// Flash-attention per head. Head n at column base n*64, s-stride 4096.
// Block: 64 q-rows of one head; loops over 64-wide t tiles with online softmax.
// scores = (q.k + mask) * (1/sqrt(64))  [mask added BEFORE scaling, faithful]
// ---------------------------------------------------------------------------
#define ATTN_SMEM_FLOATS (3*64*65 + 64*64 + 3*64)
__global__ __launch_bounds__(256) void attn_kernel(
    const float* __restrict__ q, const float* __restrict__ k,
    const float* __restrict__ v, const float* __restrict__ mask,
    float* __restrict__ u)
{
    extern __shared__ float sm[];
    float* Qs = sm;                 // [64][65] transposed: Qs[kk*65+row]
    float* Ks = Qs + 64 * 65;       // [64][65] transposed
    float* Vs = Ks + 64 * 65;       // [64][64] direct:   Vs[row*64+c]
    float* Ps = Vs + 64 * 64;       // [64][65]
    float* rm = Ps + 64 * 65;       // running max [64]
    float* rl = rm + 64;            // running denom [64]
    float* rc = rl + 64;            // correction [64]

    const int n  = blockIdx.y;          // head index 0..63
    const int s0 = blockIdx.x * 64;
    const int tid = threadIdx.x;
    const int tx = tid & 15;
    const int ty = tid >> 4;
    const size_t nb = (size_t)n * 64;   // column base within 1024

    // load Q tile transposed
#pragma unroll
    for (int it = 0; it < 4; it++) {
        int lin = tid + it * 256;       // float4 slots 0..1023
        int row = lin >> 4;             // 0..63
        int c4  = (lin & 15) * 4;       // 0..60
        float4 vq = *(const float4*)(q + (size_t)(s0 + row) * 4096 + nb + c4);
        Qs[(c4 + 0) * 65 + row] = vq.x; Qs[(c4 + 1) * 65 + row] = vq.y;
        Qs[(c4 + 2) * 65 + row] = vq.z; Qs[(c4 + 3) * 65 + row] = vq.w;
    }
    if (tid < 64) { rm[tid] = -1e30f; rl[tid] = 0.f; }

    float o[4][4];
#pragma unroll
    for (int i = 0; i < 4; i++)
#pragma unroll
        for (int c = 0; c < 4; c++) o[i][c] = 0.f;

    for (int t0 = 0; t0 < SEQ; t0 += 64) {
        __syncthreads();   // protect K/V smem reuse + first-iter Q/rm init
#pragma unroll
        for (int it = 0; it < 4; it++) {
            int lin = tid + it * 256;
            int row = lin >> 4;
            int c4  = (lin & 15) * 4;
            float4 vk = *(const float4*)(k + (size_t)(t0 + row) * 4096 + nb + c4);
            Ks[(c4 + 0) * 65 + row] = vk.x; Ks[(c4 + 1) * 65 + row] = vk.y;
            Ks[(c4 + 2) * 65 + row] = vk.z; Ks[(c4 + 3) * 65 + row] = vk.w;
            float4 vv = *(const float4*)(v + (size_t)(t0 + row) * 4096 + nb + c4);
            *(float4*)(Vs + row * 64 + c4) = vv;
        }
        __syncthreads();

        // scores 64x64 (4x4 per thread)
        float acc[4][4];
#pragma unroll
        for (int i = 0; i < 4; i++)
#pragma unroll
            for (int j = 0; j < 4; j++) acc[i][j] = 0.f;
#pragma unroll 8
        for (int kk = 0; kk < 64; kk++) {
            float a[4], b[4];
#pragma unroll
            for (int i = 0; i < 4; i++) a[i] = Qs[kk * 65 + ty * 4 + i];
#pragma unroll
            for (int j = 0; j < 4; j++) b[j] = Ks[kk * 65 + tx * 4 + j];
#pragma unroll
            for (int i = 0; i < 4; i++)
#pragma unroll
                for (int j = 0; j < 4; j++) acc[i][j] = fmaf(a[i], b[j], acc[i][j]);
        }
#pragma unroll
        for (int i = 0; i < 4; i++) {
            int sg = s0 + ty * 4 + i;
#pragma unroll
            for (int j = 0; j < 4; j++) {
                int tg = t0 + tx * 4 + j;
                Ps[(ty * 4 + i) * 65 + tx * 4 + j] =
                    (acc[i][j] + mask[(size_t)sg * SEQ + tg]) * 0.125f;
            }
        }
        __syncthreads();

        // online softmax: 4 threads per row
        {
            int row  = tid >> 2;
            int part = tid & 3;
            float tm = -1e30f;
            for (int j = part * 16; j < part * 16 + 16; j++)
                tm = fmaxf(tm, Ps[row * 65 + j]);
            tm = fmaxf(tm, __shfl_xor_sync(0xffffffffu, tm, 1));
            tm = fmaxf(tm, __shfl_xor_sync(0xffffffffu, tm, 2));
            float old_m = rm[row];
            float new_m = fmaxf(old_m, tm);
            float sum = 0.f;
            for (int j = part * 16; j < part * 16 + 16; j++) {
                float e = __expf(Ps[row * 65 + j] - new_m);
                Ps[row * 65 + j] = e;
                sum += e;
            }
            sum += __shfl_xor_sync(0xffffffffu, sum, 1);
            sum += __shfl_xor_sync(0xffffffffu, sum, 2);
            if (part == 0) {
                float corr = __expf(old_m - new_m);
                rl[row] = rl[row] * corr + sum;
                rm[row] = new_m;
                rc[row] = corr;
            }
        }
        __syncthreads();

        // rescale + accumulate o += P @ V
        float corr_i[4];
#pragma unroll
        for (int i = 0; i < 4; i++) corr_i[i] = rc[ty * 4 + i];
#pragma unroll
        for (int i = 0; i < 4; i++)
#pragma unroll
            for (int c = 0; c < 4; c++) o[i][c] *= corr_i[i];
#pragma unroll 8
        for (int jj = 0; jj < 64; jj++) {
            float a[4], b[4];
#pragma unroll
            for (int i = 0; i < 4; i++) a[i] = Ps[(ty * 4 + i) * 65 + jj];
#pragma unroll
            for (int c = 0; c < 4; c++) b[c] = Vs[jj * 64 + tx * 4 + c];
#pragma unroll
            for (int i = 0; i < 4; i++)
#pragma unroll
                for (int c = 0; c < 4; c++) o[i][c] = fmaf(a[i], b[c], o[i][c]);
        }
    }

#pragma unroll
    for (int i = 0; i < 4; i++) {
        float inv = 1.f / rl[ty * 4 + i];
#pragma unroll
        for (int c = 0; c < 4; c++)
            u[(size_t)(s0 + ty * 4 + i) * 4096 + nb + tx * 4 + c] = o[i][c] * inv;
    }
}

// ---------------------------------------------------------------------------
// LayerNorm over last dim (1024), one block per row.
// ---------------------------------------------------------------------------
__global__ __launch_bounds__(256) void ln_kernel(
    const float* __restrict__ in, const float* __restrict__ g,
    const float* __restrict__ be, float* __restrict__ out)
{
    const int row = blockIdx.x;
    const int tid = threadIdx.x;
    __shared__ float red[8];
    __shared__ float s_mu, s_rstd;

    float4 v = *(const float4*)(in + (size_t)row * DMODEL + tid * 4);
    float s = v.x + v.y + v.z + v.w;
#pragma unroll
    for (int o = 16; o > 0; o >>= 1) s += __shfl_xor_sync(0xffffffffu, s, o);
    if ((tid & 31) == 0) red[tid >> 5] = s;
    __syncthreads();
    if (tid < 8) {
        float t = red[tid];
#pragma unroll
        for (int o = 4; o > 0; o >>= 1) t += __shfl_xor_sync(0xffu, t, o);
        if (tid == 0) s_mu = t * (1.f / DMODEL);
    }
    __syncthreads();
    float mu = s_mu;
    float d0 = v.x - mu, d1 = v.y - mu, d2 = v.z - mu, d3 = v.w - mu;
    float s2 = d0 * d0 + d1 * d1 + d2 * d2 + d3 * d3;
#pragma unroll
    for (int o = 16; o > 0; o >>= 1) s2 += __shfl_xor_sync(0xffffffffu, s2, o);
    if ((tid & 31) == 0) red[tid >> 5] = s2;
    __syncthreads();
    if (tid < 8) {
        float t = red[tid];
#pragma unroll
        for (int o = 4; o > 0; o >>= 1) t += __shfl_xor_sync(0xffu, t, o);
        if (tid == 0) s_rstd = rsqrtf(t * (1.f / DMODEL) + LN_EPS);
    }
    __syncthreads();
    float rstd = s_rstd;
    float4 gv = *(const float4*)(g + tid * 4);
    float4 bv = *(const float4*)(be + tid * 4);
    float4 ov;
    ov.x = d0 * rstd * gv.x + bv.x;
    ov.y = d1 * rstd * gv.y + bv.y;
    ov.z = d2 * rstd * gv.z + bv.z;
    ov.w = d3 * rstd * gv.w + bv.w;
    *(float4*)(out + (size_t)row * DMODEL + tid * 4) = ov;
}

// ---------------------------------------------------------------------------
extern "C" void kernel_launch(void* const* d_in, const int* in_sizes, int n_in,
                              void* d_out, int out_size)
{
    const float* x    = (const float*)d_in[0];
    const float* mask = (const float*)d_in[1];
    const float* Wq   = (const float*)d_in[2];
    const float* Wk   = (const float*)d_in[3];
    const float* Wv   = (const float*)d_in[4];
    const float* Wc   = (const float*)d_in[5];
    const float* W1   = (const float*)d_in[6];
    const float* b1   = (const float*)d_in[7];
    const float* W2   = (const float*)d_in[8];
    const float* b2   = (const float*)d_in[9];
    const float* g1   = (const float*)d_in[10];
    const float* be1  = (const float*)d_in[11];
    const float* g2   = (const float*)d_in[12];
    const float* be2  = (const float*)d_in[13];
    float* out = (float*)d_out;

    float *q, *k, *v, *u, *hid;
    cudaGetSymbolAddress((void**)&q,   g_q);
    cudaGetSymbolAddress((void**)&k,   g_k);
    cudaGetSymbolAddress((void**)&v,   g_v);
    cudaGetSymbolAddress((void**)&u,   g_u);
    cudaGetSymbolAddress((void**)&hid, g_hid);

    const int attn_smem = ATTN_SMEM_FLOATS * sizeof(float);
    cudaFuncSetAttribute(attn_kernel, cudaFuncAttributeMaxDynamicSharedMemorySize, attn_smem);

    dim3 blk(256);
    dim3 gP(DMODEL / 128, MROWS / 128);   // (8, 64)
    dim3 gF1(FFDIM / 128, MROWS / 128);   // (32, 64)

    // QKV projections
    sgemm128<<<gP, blk>>>(x, Wq, nullptr, nullptr, q, DMODEL, DMODEL, 0);
    sgemm128<<<gP, blk>>>(x, Wk, nullptr, nullptr, k, DMODEL, DMODEL, 0);
    sgemm128<<<gP, blk>>>(x, Wv, nullptr, nullptr, v, DMODEL, DMODEL, 0);

    // attention -> u
    attn_kernel<<<dim3(SEQ / 64, NH), blk, attn_smem>>>(q, k, v, mask, u);

    // x + u @ Wc^T -> q (reused);  LN1 -> k (reused)
    sgemm128<<<gP, blk>>>(u, Wc, nullptr, x, q, DMODEL, DMODEL, 3);
    ln_kernel<<<MROWS, blk>>>(q, g1, be1, k);

    // FFN: relu(k@W1^T+b1) -> hid;  hid@W2^T+b2 + k -> v;  LN2 -> out
    sgemm128<<<gF1, blk>>>(k, W1, b1, nullptr, hid, FFDIM, DMODEL, 1);
    sgemm128<<<gP, blk>>>(hid, W2, b2, k, v, DMODEL, FFDIM, 2);
    ln_kernel<<<MROWS, blk>>>(v, g2, be2, out);
}

// round 2
// speedup vs baseline: 1.5051x; 1.5051x over previous
#include <cuda_runtime.h>
#include <math.h>
#include <stdint.h>

// ---------------------------------------------------------------------------
// PTransformerBlock: S=2048 B=4 D=1024 H=16 K=64 FF=4096.
// Round 2: GEMMs on tensor cores via mma.sync tf32 (m16n8k8).
// ---------------------------------------------------------------------------

#define SEQ   2048
#define BATCH 4
#define DMODEL 1024
#define NH    64            // B*H
#define FFDIM 4096
#define MROWS (SEQ*BATCH)   // 8192
#define LN_EPS 1e-5f

// scratch (allocation-free: device globals)
__device__ float g_q[MROWS * DMODEL];
__device__ float g_k[MROWS * DMODEL];
__device__ float g_v[MROWS * DMODEL];
__device__ float g_u[MROWS * DMODEL];
__device__ float g_hid[MROWS * FFDIM];

__device__ __forceinline__ float tf32r(float x) {
    uint32_t u;
    asm("cvt.rna.tf32.f32 %0, %1;" : "=r"(u) : "f"(x));
    return __uint_as_float(u);
}

// ---------------------------------------------------------------------------
// TF32 tensor-core GEMM: C[M,N] = A[M,Kd] * W[N,Kd]^T (+ epilogue)
// Block tile 128x128, BK=32, 256 threads = 8 warps of 64x32 warp tiles.
// mma.sync.aligned.m16n8k8.row.col.f32.tf32.tf32.f32
// EPI: 0=none  1=+bias,relu  2=+bias,+res  3=+res
// M % 128 == 0, N % 128 == 0, Kd % 32 == 0 (true for all call sites).
// ---------------------------------------------------------------------------
#define PADK 36   // 32 + 4: frag LDS bank = (4*gr + tig) % 32 -> conflict-free

__global__ __launch_bounds__(256) void gemm_tc(
    const float* __restrict__ A, const float* __restrict__ W,
    const float* __restrict__ bias, const float* __restrict__ res,
    float* __restrict__ C, int N, int Kd, int EPI)
{
    __shared__ float As[128][PADK];
    __shared__ float Bs[128][PADK];

    const int tid  = threadIdx.x;
    const int warp = tid >> 5;
    const int lane = tid & 31;
    const int gr   = lane >> 2;      // groupID
    const int tig  = lane & 3;       // thread-in-group
    const int wm   = (warp & 1) * 64;
    const int wn   = (warp >> 1) * 32;
    const int m0   = blockIdx.y * 128;
    const int n0   = blockIdx.x * 128;

    float acc[4][4][4];
#pragma unroll
    for (int mt = 0; mt < 4; mt++)
#pragma unroll
        for (int nt = 0; nt < 4; nt++)
#pragma unroll
            for (int c = 0; c < 4; c++) acc[mt][nt][c] = 0.f;

    for (int k0 = 0; k0 < Kd; k0 += 32) {
        // load 128x32 tiles of A and W, tf32-round once at store time
#pragma unroll
        for (int it = 0; it < 4; it++) {
            int lin = tid + it * 256;      // 0..1023 float4 slots
            int row = lin >> 3;            // 0..127
            int c4  = (lin & 7) * 4;       // 0..28
            float4 va = *(const float4*)(A + (size_t)(m0 + row) * Kd + k0 + c4);
            va.x = tf32r(va.x); va.y = tf32r(va.y);
            va.z = tf32r(va.z); va.w = tf32r(va.w);
            *(float4*)(&As[row][c4]) = va;
            float4 vb = *(const float4*)(W + (size_t)(n0 + row) * Kd + k0 + c4);
            vb.x = tf32r(vb.x); vb.y = tf32r(vb.y);
            vb.z = tf32r(vb.z); vb.w = tf32r(vb.w);
            *(float4*)(&Bs[row][c4]) = vb;
        }
        __syncthreads();

#pragma unroll
        for (int ks = 0; ks < 32; ks += 8) {
            uint32_t a[4][4], b[4][2];
#pragma unroll
            for (int mt = 0; mt < 4; mt++) {
                int r = wm + mt * 16;
                a[mt][0] = __float_as_uint(As[r + gr    ][ks + tig    ]);
                a[mt][1] = __float_as_uint(As[r + gr + 8][ks + tig    ]);
                a[mt][2] = __float_as_uint(As[r + gr    ][ks + tig + 4]);
                a[mt][3] = __float_as_uint(As[r + gr + 8][ks + tig + 4]);
            }
#pragma unroll
            for (int nt = 0; nt < 4; nt++) {
                int cc = wn + nt * 8;
                b[nt][0] = __float_as_uint(Bs[cc + gr][ks + tig    ]);
                b[nt][1] = __float_as_uint(Bs[cc + gr][ks + tig + 4]);
            }
#pragma unroll
            for (int mt = 0; mt < 4; mt++)
#pragma unroll
                for (int nt = 0; nt < 4; nt++) {
                    asm volatile(
                        "mma.sync.aligned.m16n8k8.row.col.f32.tf32.tf32.f32 "
                        "{%0,%1,%2,%3}, {%4,%5,%6,%7}, {%8,%9}, {%0,%1,%2,%3};"
                        : "+f"(acc[mt][nt][0]), "+f"(acc[mt][nt][1]),
                          "+f"(acc[mt][nt][2]), "+f"(acc[mt][nt][3])
                        : "r"(a[mt][0]), "r"(a[mt][1]), "r"(a[mt][2]), "r"(a[mt][3]),
                          "r"(b[nt][0]), "r"(b[nt][1]));
                }
        }
        __syncthreads();
    }

    // epilogue: c0,c1 at (row, col..col+1); c2,c3 at (row+8, col..col+1)
#pragma unroll
    for (int mt = 0; mt < 4; mt++) {
#pragma unroll
        for (int nt = 0; nt < 4; nt++) {
            int row = m0 + wm + mt * 16 + gr;
            int col = n0 + wn + nt * 8 + 2 * tig;
#pragma unroll
            for (int h = 0; h < 2; h++) {
                int r = row + h * 8;
                float c0 = acc[mt][nt][h * 2 + 0];
                float c1 = acc[mt][nt][h * 2 + 1];
                if (EPI == 1) {
                    c0 = fmaxf(c0 + bias[col], 0.f);
                    c1 = fmaxf(c1 + bias[col + 1], 0.f);
                } else if (EPI == 2) {
                    const float2 rv = *(const float2*)(res + (size_t)r * N + col);
                    c0 += bias[col] + rv.x;
                    c1 += bias[col + 1] + rv.y;
                } else if (EPI == 3) {
                    const float2 rv = *(const float2*)(res + (size_t)r * N + col);
                    c0 += rv.x;
                    c1 += rv.y;
                }
                float2 o; o.x = c0; o.y = c1;
                *(float2*)(C + (size_t)r * N + col) = o;
            }
        }
    }
}

// ---------------------------------------------------------------------------
// Flash-attention per head (unchanged from round 1).
// ---------------------------------------------------------------------------
#define ATTN_SMEM_FLOATS (3*64*65 + 64*64 + 3*64)
__global__ __launch_bounds__(256) void attn_kernel(
    const float* __restrict__ q, const float* __restrict__ k,
    const float* __restrict__ v, const float* __restrict__ mask,
    float* __restrict__ u)
{
    extern __shared__ float sm[];
    float* Qs = sm;                 // [64][65] transposed: Qs[kk*65+row]
    float* Ks = Qs + 64 * 65;       // [64][65] transposed
    float* Vs = Ks + 64 * 65;       // [64][64] direct
    float* Ps = Vs + 64 * 64;       // [64][65]
    float* rm = Ps + 64 * 65;
    float* rl = rm + 64;
    float* rc = rl + 64;

    const int n  = blockIdx.y;
    const int s0 = blockIdx.x * 64;
    const int tid = threadIdx.x;
    const int tx = tid & 15;
    const int ty = tid >> 4;
    const size_t nb = (size_t)n * 64;

#pragma unroll
    for (int it = 0; it < 4; it++) {
        int lin = tid + it * 256;
        int row = lin >> 4;
        int c4  = (lin & 15) * 4;
        float4 vq = *(const float4*)(q + (size_t)(s0 + row) * 4096 + nb + c4);
        Qs[(c4 + 0) * 65 + row] = vq.x; Qs[(c4 + 1) * 65 + row] = vq.y;
        Qs[(c4 + 2) * 65 + row] = vq.z; Qs[(c4 + 3) * 65 + row] = vq.w;
    }
    if (tid < 64) { rm[tid] = -1e30f; rl[tid] = 0.f; }

    float o[4][4];
#pragma unroll
    for (int i = 0; i < 4; i++)
#pragma unroll
        for (int c = 0; c < 4; c++) o[i][c] = 0.f;

    for (int t0 = 0; t0 < SEQ; t0 += 64) {
        __syncthreads();
#pragma unroll
        for (int it = 0; it < 4; it++) {
            int lin = tid + it * 256;
            int row = lin >> 4;
            int c4  = (lin & 15) * 4;
            float4 vk = *(const float4*)(k + (size_t)(t0 + row) * 4096 + nb + c4);
            Ks[(c4 + 0) * 65 + row] = vk.x; Ks[(c4 + 1) * 65 + row] = vk.y;
            Ks[(c4 + 2) * 65 + row] = vk.z; Ks[(c4 + 3) * 65 + row] = vk.w;
            float4 vv = *(const float4*)(v + (size_t)(t0 + row) * 4096 + nb + c4);
            *(float4*)(Vs + row * 64 + c4) = vv;
        }
        __syncthreads();

        float acc[4][4];
#pragma unroll
        for (int i = 0; i < 4; i++)
#pragma unroll
            for (int j = 0; j < 4; j++) acc[i][j] = 0.f;
#pragma unroll 8
        for (int kk = 0; kk < 64; kk++) {
            float a[4], b[4];
#pragma unroll
            for (int i = 0; i < 4; i++) a[i] = Qs[kk * 65 + ty * 4 + i];
#pragma unroll
            for (int j = 0; j < 4; j++) b[j] = Ks[kk * 65 + tx * 4 + j];
#pragma unroll
            for (int i = 0; i < 4; i++)
#pragma unroll
                for (int j = 0; j < 4; j++) acc[i][j] = fmaf(a[i], b[j], acc[i][j]);
        }
#pragma unroll
        for (int i = 0; i < 4; i++) {
            int sg = s0 + ty * 4 + i;
#pragma unroll
            for (int j = 0; j < 4; j++) {
                int tg = t0 + tx * 4 + j;
                Ps[(ty * 4 + i) * 65 + tx * 4 + j] =
                    (acc[i][j] + mask[(size_t)sg * SEQ + tg]) * 0.125f;
            }
        }
        __syncthreads();

        {
            int row  = tid >> 2;
            int part = tid & 3;
            float tm = -1e30f;
            for (int j = part * 16; j < part * 16 + 16; j++)
                tm = fmaxf(tm, Ps[row * 65 + j]);
            tm = fmaxf(tm, __shfl_xor_sync(0xffffffffu, tm, 1));
            tm = fmaxf(tm, __shfl_xor_sync(0xffffffffu, tm, 2));
            float old_m = rm[row];
            float new_m = fmaxf(old_m, tm);
            float sum = 0.f;
            for (int j = part * 16; j < part * 16 + 16; j++) {
                float e = __expf(Ps[row * 65 + j] - new_m);
                Ps[row * 65 + j] = e;
                sum += e;
            }
            sum += __shfl_xor_sync(0xffffffffu, sum, 1);
            sum += __shfl_xor_sync(0xffffffffu, sum, 2);
            if (part == 0) {
                float corr = __expf(old_m - new_m);
                rl[row] = rl[row] * corr + sum;
                rm[row] = new_m;
                rc[row] = corr;
            }
        }
        __syncthreads();

        float corr_i[4];
#pragma unroll
        for (int i = 0; i < 4; i++) corr_i[i] = rc[ty * 4 + i];
#pragma unroll
        for (int i = 0; i < 4; i++)
#pragma unroll
            for (int c = 0; c < 4; c++) o[i][c] *= corr_i[i];
#pragma unroll 8
        for (int jj = 0; jj < 64; jj++) {
            float a[4], b[4];
#pragma unroll
            for (int i = 0; i < 4; i++) a[i] = Ps[(ty * 4 + i) * 65 + jj];
#pragma unroll
            for (int c = 0; c < 4; c++) b[c] = Vs[jj * 64 + tx * 4 + c];
#pragma unroll
            for (int i = 0; i < 4; i++)
#pragma unroll
                for (int c = 0; c < 4; c++) o[i][c] = fmaf(a[i], b[c], o[i][c]);
        }
    }

#pragma unroll
    for (int i = 0; i < 4; i++) {
        float inv = 1.f / rl[ty * 4 + i];
#pragma unroll
        for (int c = 0; c < 4; c++)
            u[(size_t)(s0 + ty * 4 + i) * 4096 + nb + tx * 4 + c] = o[i][c] * inv;
    }
}

// ---------------------------------------------------------------------------
// LayerNorm over last dim (1024), one block per row.
// ---------------------------------------------------------------------------
__global__ __launch_bounds__(256) void ln_kernel(
    const float* __restrict__ in, const float* __restrict__ g,
    const float* __restrict__ be, float* __restrict__ out)
{
    const int row = blockIdx.x;
    const int tid = threadIdx.x;
    __shared__ float red[8];
    __shared__ float s_mu, s_rstd;

    float4 v = *(const float4*)(in + (size_t)row * DMODEL + tid * 4);
    float s = v.x + v.y + v.z + v.w;
#pragma unroll
    for (int o = 16; o > 0; o >>= 1) s += __shfl_xor_sync(0xffffffffu, s, o);
    if ((tid & 31) == 0) red[tid >> 5] = s;
    __syncthreads();
    if (tid < 8) {
        float t = red[tid];
#pragma unroll
        for (int o = 4; o > 0; o >>= 1) t += __shfl_xor_sync(0xffu, t, o);
        if (tid == 0) s_mu = t * (1.f / DMODEL);
    }
    __syncthreads();
    float mu = s_mu;
    float d0 = v.x - mu, d1 = v.y - mu, d2 = v.z - mu, d3 = v.w - mu;
    float s2 = d0 * d0 + d1 * d1 + d2 * d2 + d3 * d3;
#pragma unroll
    for (int o = 16; o > 0; o >>= 1) s2 += __shfl_xor_sync(0xffffffffu, s2, o);
    if ((tid & 31) == 0) red[tid >> 5] = s2;
    __syncthreads();
    if (tid < 8) {
        float t = red[tid];
#pragma unroll
        for (int o = 4; o > 0; o >>= 1) t += __shfl_xor_sync(0xffu, t, o);
        if (tid == 0) s_rstd = rsqrtf(t * (1.f / DMODEL) + LN_EPS);
    }
    __syncthreads();
    float rstd = s_rstd;
    float4 gv = *(const float4*)(g + tid * 4);
    float4 bv = *(const float4*)(be + tid * 4);
    float4 ov;
    ov.x = d0 * rstd * gv.x + bv.x;
    ov.y = d1 * rstd * gv.y + bv.y;
    ov.z = d2 * rstd * gv.z + bv.z;
    ov.w = d3 * rstd * gv.w + bv.w;
    *(float4*)(out + (size_t)row * DMODEL + tid * 4) = ov;
}

// ---------------------------------------------------------------------------
extern "C" void kernel_launch(void* const* d_in, const int* in_sizes, int n_in,
                              void* d_out, int out_size)
{
    const float* x    = (const float*)d_in[0];
    const float* mask = (const float*)d_in[1];
    const float* Wq   = (const float*)d_in[2];
    const float* Wk   = (const float*)d_in[3];
    const float* Wv   = (const float*)d_in[4];
    const float* Wc   = (const float*)d_in[5];
    const float* W1   = (const float*)d_in[6];
    const float* b1   = (const float*)d_in[7];
    const float* W2   = (const float*)d_in[8];
    const float* b2   = (const float*)d_in[9];
    const float* g1   = (const float*)d_in[10];
    const float* be1  = (const float*)d_in[11];
    const float* g2   = (const float*)d_in[12];
    const float* be2  = (const float*)d_in[13];
    float* out = (float*)d_out;

    float *q, *k, *v, *u, *hid;
    cudaGetSymbolAddress((void**)&q,   g_q);
    cudaGetSymbolAddress((void**)&k,   g_k);
    cudaGetSymbolAddress((void**)&v,   g_v);
    cudaGetSymbolAddress((void**)&u,   g_u);
    cudaGetSymbolAddress((void**)&hid, g_hid);

    const int attn_smem = ATTN_SMEM_FLOATS * sizeof(float);
    cudaFuncSetAttribute(attn_kernel, cudaFuncAttributeMaxDynamicSharedMemorySize, attn_smem);

    dim3 blk(256);
    dim3 gP(DMODEL / 128, MROWS / 128);   // (8, 64)
    dim3 gF1(FFDIM / 128, MROWS / 128);   // (32, 64)

    // QKV projections (tensor cores, tf32)
    gemm_tc<<<gP, blk>>>(x, Wq, nullptr, nullptr, q, DMODEL, DMODEL, 0);
    gemm_tc<<<gP, blk>>>(x, Wk, nullptr, nullptr, k, DMODEL, DMODEL, 0);
    gemm_tc<<<gP, blk>>>(x, Wv, nullptr, nullptr, v, DMODEL, DMODEL, 0);

    // attention -> u
    attn_kernel<<<dim3(SEQ / 64, NH), blk, attn_smem>>>(q, k, v, mask, u);

    // x + u @ Wc^T -> q (reused);  LN1 -> k (reused)
    gemm_tc<<<gP, blk>>>(u, Wc, nullptr, x, q, DMODEL, DMODEL, 3);
    ln_kernel<<<MROWS, blk>>>(q, g1, be1, k);

    // FFN: relu(k@W1^T+b1) -> hid;  hid@W2^T+b2 + k -> v;  LN2 -> out
    gemm_tc<<<gF1, blk>>>(k, W1, b1, nullptr, hid, FFDIM, DMODEL, 1);
    gemm_tc<<<gP, blk>>>(hid, W2, b2, k, v, DMODEL, FFDIM, 2);
    ln_kernel<<<MROWS, blk>>>(v, g2, be2, out);
}

// round 4
// speedup vs baseline: 1.9530x; 1.2976x over previous
#include <cuda_runtime.h>
#include <math.h>
#include <stdint.h>

// ---------------------------------------------------------------------------
// PTransformerBlock: S=2048 B=4 D=1024 H=16 K=64 FF=4096.
// Round 4 (= round 3 resubmit after infra failure):
// attention matmuls on tensor cores (tf32 m16n8k8) + flash softmax.
// ---------------------------------------------------------------------------

#define SEQ   2048
#define BATCH 4
#define DMODEL 1024
#define NH    64            // B*H
#define FFDIM 4096
#define MROWS (SEQ*BATCH)   // 8192
#define LN_EPS 1e-5f

// scratch (allocation-free: device globals)
__device__ float g_q[MROWS * DMODEL];
__device__ float g_k[MROWS * DMODEL];
__device__ float g_v[MROWS * DMODEL];
__device__ float g_u[MROWS * DMODEL];
__device__ float g_hid[MROWS * FFDIM];

__device__ __forceinline__ float tf32r(float x) {
    uint32_t u;
    asm("cvt.rna.tf32.f32 %0, %1;" : "=r"(u) : "f"(x));
    return __uint_as_float(u);
}

__device__ __forceinline__ void mma_tf32(
    float& d0, float& d1, float& d2, float& d3,
    uint32_t a0, uint32_t a1, uint32_t a2, uint32_t a3,
    uint32_t b0, uint32_t b1)
{
    asm volatile(
        "mma.sync.aligned.m16n8k8.row.col.f32.tf32.tf32.f32 "
        "{%0,%1,%2,%3}, {%4,%5,%6,%7}, {%8,%9}, {%0,%1,%2,%3};"
        : "+f"(d0), "+f"(d1), "+f"(d2), "+f"(d3)
        : "r"(a0), "r"(a1), "r"(a2), "r"(a3), "r"(b0), "r"(b1));
}

// ---------------------------------------------------------------------------
// TF32 tensor-core GEMM: C[M,N] = A[M,Kd] * W[N,Kd]^T (+ epilogue)
// Block tile 128x128, BK=32, 256 threads = 8 warps of 64x32 warp tiles.
// EPI: 0=none  1=+bias,relu  2=+bias,+res  3=+res
// ---------------------------------------------------------------------------
#define PADK 36

__global__ __launch_bounds__(256) void gemm_tc(
    const float* __restrict__ A, const float* __restrict__ W,
    const float* __restrict__ bias, const float* __restrict__ res,
    float* __restrict__ C, int N, int Kd, int EPI)
{
    __shared__ float As[128][PADK];
    __shared__ float Bs[128][PADK];

    const int tid  = threadIdx.x;
    const int warp = tid >> 5;
    const int lane = tid & 31;
    const int gr   = lane >> 2;
    const int tig  = lane & 3;
    const int wm   = (warp & 1) * 64;
    const int wn   = (warp >> 1) * 32;
    const int m0   = blockIdx.y * 128;
    const int n0   = blockIdx.x * 128;

    float acc[4][4][4];
#pragma unroll
    for (int mt = 0; mt < 4; mt++)
#pragma unroll
        for (int nt = 0; nt < 4; nt++)
#pragma unroll
            for (int c = 0; c < 4; c++) acc[mt][nt][c] = 0.f;

    for (int k0 = 0; k0 < Kd; k0 += 32) {
#pragma unroll
        for (int it = 0; it < 4; it++) {
            int lin = tid + it * 256;
            int row = lin >> 3;
            int c4  = (lin & 7) * 4;
            float4 va = *(const float4*)(A + (size_t)(m0 + row) * Kd + k0 + c4);
            va.x = tf32r(va.x); va.y = tf32r(va.y);
            va.z = tf32r(va.z); va.w = tf32r(va.w);
            *(float4*)(&As[row][c4]) = va;
            float4 vb = *(const float4*)(W + (size_t)(n0 + row) * Kd + k0 + c4);
            vb.x = tf32r(vb.x); vb.y = tf32r(vb.y);
            vb.z = tf32r(vb.z); vb.w = tf32r(vb.w);
            *(float4*)(&Bs[row][c4]) = vb;
        }
        __syncthreads();

#pragma unroll
        for (int ks = 0; ks < 32; ks += 8) {
            uint32_t a[4][4], b[4][2];
#pragma unroll
            for (int mt = 0; mt < 4; mt++) {
                int r = wm + mt * 16;
                a[mt][0] = __float_as_uint(As[r + gr    ][ks + tig    ]);
                a[mt][1] = __float_as_uint(As[r + gr + 8][ks + tig    ]);
                a[mt][2] = __float_as_uint(As[r + gr    ][ks + tig + 4]);
                a[mt][3] = __float_as_uint(As[r + gr + 8][ks + tig + 4]);
            }
#pragma unroll
            for (int nt = 0; nt < 4; nt++) {
                int cc = wn + nt * 8;
                b[nt][0] = __float_as_uint(Bs[cc + gr][ks + tig    ]);
                b[nt][1] = __float_as_uint(Bs[cc + gr][ks + tig + 4]);
            }
#pragma unroll
            for (int mt = 0; mt < 4; mt++)
#pragma unroll
                for (int nt = 0; nt < 4; nt++)
                    mma_tf32(acc[mt][nt][0], acc[mt][nt][1], acc[mt][nt][2], acc[mt][nt][3],
                             a[mt][0], a[mt][1], a[mt][2], a[mt][3],
                             b[nt][0], b[nt][1]);
        }
        __syncthreads();
    }

#pragma unroll
    for (int mt = 0; mt < 4; mt++) {
#pragma unroll
        for (int nt = 0; nt < 4; nt++) {
            int row = m0 + wm + mt * 16 + gr;
            int col = n0 + wn + nt * 8 + 2 * tig;
#pragma unroll
            for (int h = 0; h < 2; h++) {
                int r = row + h * 8;
                float c0 = acc[mt][nt][h * 2 + 0];
                float c1 = acc[mt][nt][h * 2 + 1];
                if (EPI == 1) {
                    c0 = fmaxf(c0 + bias[col], 0.f);
                    c1 = fmaxf(c1 + bias[col + 1], 0.f);
                } else if (EPI == 2) {
                    const float2 rv = *(const float2*)(res + (size_t)r * N + col);
                    c0 += bias[col] + rv.x;
                    c1 += bias[col + 1] + rv.y;
                } else if (EPI == 3) {
                    const float2 rv = *(const float2*)(res + (size_t)r * N + col);
                    c0 += rv.x;
                    c1 += rv.y;
                }
                float2 o; o.x = c0; o.y = c1;
                *(float2*)(C + (size_t)r * N + col) = o;
            }
        }
    }
}

// ---------------------------------------------------------------------------
// Tensor-core flash attention. One block = 64 q-rows of one head.
// 8 warps: warp tile 16(m) x 32(n); online softmax via smem rows.
// ---------------------------------------------------------------------------
#define APAD 68
#define ATTN_SMEM_FLOATS (4*64*APAD + 3*64)

__global__ __launch_bounds__(256) void attn_tc(
    const float* __restrict__ q, const float* __restrict__ k,
    const float* __restrict__ v, const float* __restrict__ mask,
    float* __restrict__ u)
{
    extern __shared__ float sm[];
    float* Qs = sm;                  // [64][APAD] tf32-rounded
    float* Ks = Qs + 64 * APAD;      // [64][APAD] tf32-rounded
    float* Vs = Ks + 64 * APAD;      // [64][APAD] tf32-rounded, natural [t][c]
    float* Ps = Vs + 64 * APAD;      // [64][APAD] scores / probs
    float* rm = Ps + 64 * APAD;      // running max [64]
    float* rl = rm + 64;             // running denom [64]
    float* rc = rl + 64;             // correction [64]

    const int n   = blockIdx.y;
    const int s0  = blockIdx.x * 64;
    const int tid = threadIdx.x;
    const int warp = tid >> 5;
    const int lane = tid & 31;
    const int gr   = lane >> 2;
    const int tig  = lane & 3;
    const int wm   = (warp & 3) * 16;
    const int wn   = (warp >> 2) * 32;
    const size_t nb = (size_t)n * 64;

    // load Q tile (tf32-rounded)
#pragma unroll
    for (int it = 0; it < 4; it++) {
        int lin = tid + it * 256;
        int row = lin >> 4;
        int c4  = (lin & 15) * 4;
        float4 vq = *(const float4*)(q + (size_t)(s0 + row) * 4096 + nb + c4);
        vq.x = tf32r(vq.x); vq.y = tf32r(vq.y);
        vq.z = tf32r(vq.z); vq.w = tf32r(vq.w);
        *(float4*)(&Qs[row * APAD + c4]) = vq;
    }
    if (tid < 64) { rm[tid] = -1e30f; rl[tid] = 0.f; }

    float oacc[4][4];
#pragma unroll
    for (int nt = 0; nt < 4; nt++)
#pragma unroll
        for (int c = 0; c < 4; c++) oacc[nt][c] = 0.f;

    for (int t0 = 0; t0 < SEQ; t0 += 64) {
        __syncthreads();   // protect K/V/P smem reuse + first-iter init
        // load K, V tiles
#pragma unroll
        for (int it = 0; it < 4; it++) {
            int lin = tid + it * 256;
            int row = lin >> 4;
            int c4  = (lin & 15) * 4;
            float4 vk = *(const float4*)(k + (size_t)(t0 + row) * 4096 + nb + c4);
            vk.x = tf32r(vk.x); vk.y = tf32r(vk.y);
            vk.z = tf32r(vk.z); vk.w = tf32r(vk.w);
            *(float4*)(&Ks[row * APAD + c4]) = vk;
            float4 vv = *(const float4*)(v + (size_t)(t0 + row) * 4096 + nb + c4);
            vv.x = tf32r(vv.x); vv.y = tf32r(vv.y);
            vv.z = tf32r(vv.z); vv.w = tf32r(vv.w);
            *(float4*)(&Vs[row * APAD + c4]) = vv;
        }
        __syncthreads();

        // S = Q K^T   (warp tile 16x32)
        float sacc[4][4];
#pragma unroll
        for (int nt = 0; nt < 4; nt++)
#pragma unroll
            for (int c = 0; c < 4; c++) sacc[nt][c] = 0.f;
#pragma unroll
        for (int ks = 0; ks < 64; ks += 8) {
            uint32_t a0 = __float_as_uint(Qs[(wm + gr    ) * APAD + ks + tig    ]);
            uint32_t a1 = __float_as_uint(Qs[(wm + gr + 8) * APAD + ks + tig    ]);
            uint32_t a2 = __float_as_uint(Qs[(wm + gr    ) * APAD + ks + tig + 4]);
            uint32_t a3 = __float_as_uint(Qs[(wm + gr + 8) * APAD + ks + tig + 4]);
#pragma unroll
            for (int nt = 0; nt < 4; nt++) {
                int cc = wn + nt * 8;
                uint32_t b0 = __float_as_uint(Ks[(cc + gr) * APAD + ks + tig    ]);
                uint32_t b1 = __float_as_uint(Ks[(cc + gr) * APAD + ks + tig + 4]);
                mma_tf32(sacc[nt][0], sacc[nt][1], sacc[nt][2], sacc[nt][3],
                         a0, a1, a2, a3, b0, b1);
            }
        }
        // (S + mask) * 1/sqrt(K) -> Ps   [mask added BEFORE scaling, faithful]
#pragma unroll
        for (int nt = 0; nt < 4; nt++) {
            int col = wn + nt * 8 + 2 * tig;
#pragma unroll
            for (int h = 0; h < 2; h++) {
                int r = wm + gr + h * 8;
                const float2 mv = *(const float2*)(mask + (size_t)(s0 + r) * SEQ + t0 + col);
                Ps[r * APAD + col    ] = (sacc[nt][h * 2 + 0] + mv.x) * 0.125f;
                Ps[r * APAD + col + 1] = (sacc[nt][h * 2 + 1] + mv.y) * 0.125f;
            }
        }
        __syncthreads();

        // online softmax: 4 threads per row, 16 cols each
        {
            int row  = tid >> 2;
            int part = tid & 3;
            float tm = -1e30f;
#pragma unroll
            for (int j = part * 16; j < part * 16 + 16; j++)
                tm = fmaxf(tm, Ps[row * APAD + j]);
            tm = fmaxf(tm, __shfl_xor_sync(0xffffffffu, tm, 1));
            tm = fmaxf(tm, __shfl_xor_sync(0xffffffffu, tm, 2));
            float old_m = rm[row];
            float new_m = fmaxf(old_m, tm);
            float sum = 0.f;
#pragma unroll
            for (int j = part * 16; j < part * 16 + 16; j++) {
                float e = __expf(Ps[row * APAD + j] - new_m);
                Ps[row * APAD + j] = tf32r(e);
                sum += e;
            }
            sum += __shfl_xor_sync(0xffffffffu, sum, 1);
            sum += __shfl_xor_sync(0xffffffffu, sum, 2);
            if (part == 0) {
                float corr = __expf(old_m - new_m);
                rl[row] = rl[row] * corr + sum;
                rm[row] = new_m;
                rc[row] = corr;
            }
        }
        __syncthreads();

        // O = O*corr + P @ V
        float c_lo = rc[wm + gr];
        float c_hi = rc[wm + gr + 8];
#pragma unroll
        for (int nt = 0; nt < 4; nt++) {
            oacc[nt][0] *= c_lo; oacc[nt][1] *= c_lo;
            oacc[nt][2] *= c_hi; oacc[nt][3] *= c_hi;
        }
#pragma unroll
        for (int ks = 0; ks < 64; ks += 8) {
            uint32_t a0 = __float_as_uint(Ps[(wm + gr    ) * APAD + ks + tig    ]);
            uint32_t a1 = __float_as_uint(Ps[(wm + gr + 8) * APAD + ks + tig    ]);
            uint32_t a2 = __float_as_uint(Ps[(wm + gr    ) * APAD + ks + tig + 4]);
            uint32_t a3 = __float_as_uint(Ps[(wm + gr + 8) * APAD + ks + tig + 4]);
#pragma unroll
            for (int nt = 0; nt < 4; nt++) {
                int cc = wn + nt * 8;
                uint32_t b0 = __float_as_uint(Vs[(ks + tig    ) * APAD + cc + gr]);
                uint32_t b1 = __float_as_uint(Vs[(ks + tig + 4) * APAD + cc + gr]);
                mma_tf32(oacc[nt][0], oacc[nt][1], oacc[nt][2], oacc[nt][3],
                         a0, a1, a2, a3, b0, b1);
            }
        }
    }

    // final normalize + store
    {
        float inv_lo = 1.f / rl[wm + gr];
        float inv_hi = 1.f / rl[wm + gr + 8];
#pragma unroll
        for (int nt = 0; nt < 4; nt++) {
            int col = wn + nt * 8 + 2 * tig;
            float2 o0; o0.x = oacc[nt][0] * inv_lo; o0.y = oacc[nt][1] * inv_lo;
            *(float2*)(u + (size_t)(s0 + wm + gr) * 4096 + nb + col) = o0;
            float2 o1; o1.x = oacc[nt][2] * inv_hi; o1.y = oacc[nt][3] * inv_hi;
            *(float2*)(u + (size_t)(s0 + wm + gr + 8) * 4096 + nb + col) = o1;
        }
    }
}

// ---------------------------------------------------------------------------
// LayerNorm over last dim (1024), one block per row.
// ---------------------------------------------------------------------------
__global__ __launch_bounds__(256) void ln_kernel(
    const float* __restrict__ in, const float* __restrict__ g,
    const float* __restrict__ be, float* __restrict__ out)
{
    const int row = blockIdx.x;
    const int tid = threadIdx.x;
    __shared__ float red[8];
    __shared__ float s_mu, s_rstd;

    float4 v = *(const float4*)(in + (size_t)row * DMODEL + tid * 4);
    float s = v.x + v.y + v.z + v.w;
#pragma unroll
    for (int o = 16; o > 0; o >>= 1) s += __shfl_xor_sync(0xffffffffu, s, o);
    if ((tid & 31) == 0) red[tid >> 5] = s;
    __syncthreads();
    if (tid < 8) {
        float t = red[tid];
#pragma unroll
        for (int o = 4; o > 0; o >>= 1) t += __shfl_xor_sync(0xffu, t, o);
        if (tid == 0) s_mu = t * (1.f / DMODEL);
    }
    __syncthreads();
    float mu = s_mu;
    float d0 = v.x - mu, d1 = v.y - mu, d2 = v.z - mu, d3 = v.w - mu;
    float s2 = d0 * d0 + d1 * d1 + d2 * d2 + d3 * d3;
#pragma unroll
    for (int o = 16; o > 0; o >>= 1) s2 += __shfl_xor_sync(0xffffffffu, s2, o);
    if ((tid & 31) == 0) red[tid >> 5] = s2;
    __syncthreads();
    if (tid < 8) {
        float t = red[tid];
#pragma unroll
        for (int o = 4; o > 0; o >>= 1) t += __shfl_xor_sync(0xffu, t, o);
        if (tid == 0) s_rstd = rsqrtf(t * (1.f / DMODEL) + LN_EPS);
    }
    __syncthreads();
    float rstd = s_rstd;
    float4 gv = *(const float4*)(g + tid * 4);
    float4 bv = *(const float4*)(be + tid * 4);
    float4 ov;
    ov.x = d0 * rstd * gv.x + bv.x;
    ov.y = d1 * rstd * gv.y + bv.y;
    ov.z = d2 * rstd * gv.z + bv.z;
    ov.w = d3 * rstd * gv.w + bv.w;
    *(float4*)(out + (size_t)row * DMODEL + tid * 4) = ov;
}

// ---------------------------------------------------------------------------
extern "C" void kernel_launch(void* const* d_in, const int* in_sizes, int n_in,
                              void* d_out, int out_size)
{
    const float* x    = (const float*)d_in[0];
    const float* mask = (const float*)d_in[1];
    const float* Wq   = (const float*)d_in[2];
    const float* Wk   = (const float*)d_in[3];
    const float* Wv   = (const float*)d_in[4];
    const float* Wc   = (const float*)d_in[5];
    const float* W1   = (const float*)d_in[6];
    const float* b1   = (const float*)d_in[7];
    const float* W2   = (const float*)d_in[8];
    const float* b2   = (const float*)d_in[9];
    const float* g1   = (const float*)d_in[10];
    const float* be1  = (const float*)d_in[11];
    const float* g2   = (const float*)d_in[12];
    const float* be2  = (const float*)d_in[13];
    float* out = (float*)d_out;

    float *q, *k, *v, *u, *hid;
    cudaGetSymbolAddress((void**)&q,   g_q);
    cudaGetSymbolAddress((void**)&k,   g_k);
    cudaGetSymbolAddress((void**)&v,   g_v);
    cudaGetSymbolAddress((void**)&u,   g_u);
    cudaGetSymbolAddress((void**)&hid, g_hid);

    const int attn_smem = ATTN_SMEM_FLOATS * sizeof(float);
    cudaFuncSetAttribute(attn_tc, cudaFuncAttributeMaxDynamicSharedMemorySize, attn_smem);

    dim3 blk(256);
    dim3 gP(DMODEL / 128, MROWS / 128);   // (8, 64)
    dim3 gF1(FFDIM / 128, MROWS / 128);   // (32, 64)

    // QKV projections (tensor cores, tf32)
    gemm_tc<<<gP, blk>>>(x, Wq, nullptr, nullptr, q, DMODEL, DMODEL, 0);
    gemm_tc<<<gP, blk>>>(x, Wk, nullptr, nullptr, k, DMODEL, DMODEL, 0);
    gemm_tc<<<gP, blk>>>(x, Wv, nullptr, nullptr, v, DMODEL, DMODEL, 0);

    // attention -> u
    attn_tc<<<dim3(SEQ / 64, NH), blk, attn_smem>>>(q, k, v, mask, u);

    // x + u @ Wc^T -> q (reused);  LN1 -> k (reused)
    gemm_tc<<<gP, blk>>>(u, Wc, nullptr, x, q, DMODEL, DMODEL, 3);
    ln_kernel<<<MROWS, blk>>>(q, g1, be1, k);

    // FFN: relu(k@W1^T+b1) -> hid;  hid@W2^T+b2 + k -> v;  LN2 -> out
    gemm_tc<<<gF1, blk>>>(k, W1, b1, nullptr, hid, FFDIM, DMODEL, 1);
    gemm_tc<<<gP, blk>>>(hid, W2, b2, k, v, DMODEL, FFDIM, 2);
    ln_kernel<<<MROWS, blk>>>(v, g2, be2, out);
}

// round 5
// speedup vs baseline: 3.0793x; 1.5767x over previous
#include <cuda_runtime.h>
#include <math.h>
#include <stdint.h>

// ---------------------------------------------------------------------------
// PTransformerBlock: S=2048 B=4 D=1024 H=16 K=64 FF=4096.
// Round 5: cp.async double-buffered TF32 GEMM (implicit truncation),
//          fused QKV projection, tensor-core flash attention.
// ---------------------------------------------------------------------------

#define SEQ   2048
#define BATCH 4
#define DMODEL 1024
#define FFDIM 4096
#define MROWS (SEQ*BATCH)   // 8192
#define LN_EPS 1e-5f

// scratch (allocation-free: device globals)
__device__ float g_qkv[MROWS * 3072];
__device__ float g_wp [3072 * DMODEL];
__device__ float g_u  [MROWS * DMODEL];
__device__ float g_t1 [MROWS * DMODEL];
__device__ float g_t2 [MROWS * DMODEL];
__device__ float g_t3 [MROWS * DMODEL];
__device__ float g_hid[MROWS * FFDIM];

__device__ __forceinline__ float tf32r(float x) {
    uint32_t u;
    asm("cvt.rna.tf32.f32 %0, %1;" : "=r"(u) : "f"(x));
    return __uint_as_float(u);
}

__device__ __forceinline__ void mma_tf32(
    float& d0, float& d1, float& d2, float& d3,
    uint32_t a0, uint32_t a1, uint32_t a2, uint32_t a3,
    uint32_t b0, uint32_t b1)
{
    asm volatile(
        "mma.sync.aligned.m16n8k8.row.col.f32.tf32.tf32.f32 "
        "{%0,%1,%2,%3}, {%4,%5,%6,%7}, {%8,%9}, {%0,%1,%2,%3};"
        : "+f"(d0), "+f"(d1), "+f"(d2), "+f"(d3)
        : "r"(a0), "r"(a1), "r"(a2), "r"(a3), "r"(b0), "r"(b1));
}

__device__ __forceinline__ void cp16(uint32_t s, const float* g) {
    asm volatile("cp.async.cg.shared.global [%0], [%1], 16;" :: "r"(s), "l"(g));
}
__device__ __forceinline__ uint32_t saddr(const void* p) {
    return (uint32_t)__cvta_generic_to_shared(p);
}

// ---------------------------------------------------------------------------
// TF32 tensor-core GEMM with cp.async 2-stage pipeline.
// C[M,N] = A[M,Kd] * W[N,Kd]^T (+ epilogue)
// Block tile 128x128, BK=32, 256 threads = 8 warps of 64x32 warp tiles.
// fp32 stored raw in smem; mma reads tf32 bits (implicit truncation).
// EPI: 0=none  1=+bias,relu  2=+bias,+res  3=+res
// ---------------------------------------------------------------------------
#define PADK 36
#define STG  (128 * PADK)                  // floats per matrix per stage
#define GEMM_SMEM_BYTES (4 * STG * 4)      // 73728

__global__ __launch_bounds__(256) void gemm_tc(
    const float* __restrict__ A, const float* __restrict__ W,
    const float* __restrict__ bias, const float* __restrict__ res,
    float* __restrict__ C, int N, int Kd, int EPI)
{
    extern __shared__ float smem[];
    float* const Ab0 = smem;
    float* const Bb0 = smem + STG;
    float* const Ab1 = smem + 2 * STG;
    float* const Bb1 = smem + 3 * STG;

    const int tid  = threadIdx.x;
    const int warp = tid >> 5;
    const int lane = tid & 31;
    const int gr   = lane >> 2;
    const int tig  = lane & 3;
    const int wm   = (warp & 1) * 64;
    const int wn   = (warp >> 1) * 32;
    const int m0   = blockIdx.y * 128;
    const int n0   = blockIdx.x * 128;

    // loader offsets (same every tile)
    const int lrow = tid >> 3;             // + it*32
    const int lc4  = (tid & 7) * 4;

    float acc[4][4][4];
#pragma unroll
    for (int mt = 0; mt < 4; mt++)
#pragma unroll
        for (int nt = 0; nt < 4; nt++)
#pragma unroll
            for (int c = 0; c < 4; c++) acc[mt][nt][c] = 0.f;

    const int ktiles = Kd >> 5;

    // prefetch tile 0 into stage 0
    {
#pragma unroll
        for (int it = 0; it < 4; it++) {
            int row = lrow + it * 32;
            cp16(saddr(Ab0 + row * PADK + lc4), A + (size_t)(m0 + row) * Kd + lc4);
            cp16(saddr(Bb0 + row * PADK + lc4), W + (size_t)(n0 + row) * Kd + lc4);
        }
        asm volatile("cp.async.commit_group;");
    }

    for (int t = 0; t < ktiles; t++) {
        if (t + 1 < ktiles) {
            float* An = ((t + 1) & 1) ? Ab1 : Ab0;
            float* Bn = ((t + 1) & 1) ? Bb1 : Bb0;
            const int k0 = (t + 1) << 5;
#pragma unroll
            for (int it = 0; it < 4; it++) {
                int row = lrow + it * 32;
                cp16(saddr(An + row * PADK + lc4), A + (size_t)(m0 + row) * Kd + k0 + lc4);
                cp16(saddr(Bn + row * PADK + lc4), W + (size_t)(n0 + row) * Kd + k0 + lc4);
            }
            asm volatile("cp.async.commit_group;");
            asm volatile("cp.async.wait_group 1;");
        } else {
            asm volatile("cp.async.wait_group 0;");
        }
        __syncthreads();

        const float* As_ = (t & 1) ? Ab1 : Ab0;
        const float* Bs_ = (t & 1) ? Bb1 : Bb0;

#pragma unroll
        for (int ks = 0; ks < 32; ks += 8) {
            uint32_t a[4][4], b[4][2];
#pragma unroll
            for (int mt = 0; mt < 4; mt++) {
                int r = wm + mt * 16;
                a[mt][0] = __float_as_uint(As_[(r + gr    ) * PADK + ks + tig    ]);
                a[mt][1] = __float_as_uint(As_[(r + gr + 8) * PADK + ks + tig    ]);
                a[mt][2] = __float_as_uint(As_[(r + gr    ) * PADK + ks + tig + 4]);
                a[mt][3] = __float_as_uint(As_[(r + gr + 8) * PADK + ks + tig + 4]);
            }
#pragma unroll
            for (int nt = 0; nt < 4; nt++) {
                int cc = wn + nt * 8;
                b[nt][0] = __float_as_uint(Bs_[(cc + gr) * PADK + ks + tig    ]);
                b[nt][1] = __float_as_uint(Bs_[(cc + gr) * PADK + ks + tig + 4]);
            }
#pragma unroll
            for (int mt = 0; mt < 4; mt++)
#pragma unroll
                for (int nt = 0; nt < 4; nt++)
                    mma_tf32(acc[mt][nt][0], acc[mt][nt][1], acc[mt][nt][2], acc[mt][nt][3],
                             a[mt][0], a[mt][1], a[mt][2], a[mt][3],
                             b[nt][0], b[nt][1]);
        }
        __syncthreads();
    }

#pragma unroll
    for (int mt = 0; mt < 4; mt++) {
#pragma unroll
        for (int nt = 0; nt < 4; nt++) {
            int row = m0 + wm + mt * 16 + gr;
            int col = n0 + wn + nt * 8 + 2 * tig;
#pragma unroll
            for (int h = 0; h < 2; h++) {
                int r = row + h * 8;
                float c0 = acc[mt][nt][h * 2 + 0];
                float c1 = acc[mt][nt][h * 2 + 1];
                if (EPI == 1) {
                    c0 = fmaxf(c0 + bias[col], 0.f);
                    c1 = fmaxf(c1 + bias[col + 1], 0.f);
                } else if (EPI == 2) {
                    const float2 rv = *(const float2*)(res + (size_t)r * N + col);
                    c0 += bias[col] + rv.x;
                    c1 += bias[col + 1] + rv.y;
                } else if (EPI == 3) {
                    const float2 rv = *(const float2*)(res + (size_t)r * N + col);
                    c0 += rv.x;
                    c1 += rv.y;
                }
                float2 o; o.x = c0; o.y = c1;
                *(float2*)(C + (size_t)r * N + col) = o;
            }
        }
    }
}

// ---------------------------------------------------------------------------
// Pack [Wq; Wk; Wv] -> Wp [3072, 1024]
// ---------------------------------------------------------------------------
__global__ __launch_bounds__(256) void pack_qkv(
    const float* __restrict__ Wq, const float* __restrict__ Wk,
    const float* __restrict__ Wv, float* __restrict__ Wp)
{
    int i = blockIdx.x * blockDim.x + threadIdx.x;     // float4 index
    int row = (i * 4) >> 10;
    int col = (i * 4) & 1023;
    const float* src;
    if (row < 1024)      src = Wq + (size_t)row * 1024 + col;
    else if (row < 2048) src = Wk + (size_t)(row - 1024) * 1024 + col;
    else                 src = Wv + (size_t)(row - 2048) * 1024 + col;
    *(float4*)(Wp + (size_t)i * 4) = *(const float4*)src;
}

// ---------------------------------------------------------------------------
// Tensor-core flash attention reading the packed qkv buffer [8192, 3072].
// Head n = b*16+h: row (s*4+b), q at col h*64, k at 1024+h*64, v at 2048+h*64.
// Output u as [2048, 4096] at (s, n*64)  (== [8192,1024] rows s*4+b).
// One block = 64 q-rows of one head; 8 warps, warp tile 16(m) x 32(n).
// ---------------------------------------------------------------------------
#define APAD 68
#define ATTN_SMEM_FLOATS (4*64*APAD + 3*64)
#define QKV_SSTRIDE (4*3072)   // row stride per s step

__global__ __launch_bounds__(256) void attn_tc(
    const float* __restrict__ qkv, const float* __restrict__ mask,
    float* __restrict__ u)
{
    extern __shared__ float sm[];
    float* Qs = sm;                  // [64][APAD]
    float* Ks = Qs + 64 * APAD;
    float* Vs = Ks + 64 * APAD;
    float* Ps = Vs + 64 * APAD;
    float* rm = Ps + 64 * APAD;
    float* rl = rm + 64;
    float* rc = rl + 64;

    const int n   = blockIdx.y;          // head 0..63 (n = b*16+h)
    const int bb  = n >> 4;
    const int hh  = n & 15;
    const int s0  = blockIdx.x * 64;
    const int tid = threadIdx.x;
    const int warp = tid >> 5;
    const int lane = tid & 31;
    const int gr   = lane >> 2;
    const int tig  = lane & 3;
    const int wm   = (warp & 3) * 16;
    const int wn   = (warp >> 2) * 32;

    const float* qb = qkv + (size_t)bb * 3072 + hh * 64;
    const float* kb = qb + 1024;
    const float* vb = qb + 2048;

    // load Q tile (tf32-rounded)
#pragma unroll
    for (int it = 0; it < 4; it++) {
        int lin = tid + it * 256;
        int row = lin >> 4;
        int c4  = (lin & 15) * 4;
        float4 vq = *(const float4*)(qb + (size_t)(s0 + row) * QKV_SSTRIDE + c4);
        vq.x = tf32r(vq.x); vq.y = tf32r(vq.y);
        vq.z = tf32r(vq.z); vq.w = tf32r(vq.w);
        *(float4*)(&Qs[row * APAD + c4]) = vq;
    }
    if (tid < 64) { rm[tid] = -1e30f; rl[tid] = 0.f; }

    float oacc[4][4];
#pragma unroll
    for (int nt = 0; nt < 4; nt++)
#pragma unroll
        for (int c = 0; c < 4; c++) oacc[nt][c] = 0.f;

    for (int t0 = 0; t0 < SEQ; t0 += 64) {
        __syncthreads();
#pragma unroll
        for (int it = 0; it < 4; it++) {
            int lin = tid + it * 256;
            int row = lin >> 4;
            int c4  = (lin & 15) * 4;
            float4 vk = *(const float4*)(kb + (size_t)(t0 + row) * QKV_SSTRIDE + c4);
            vk.x = tf32r(vk.x); vk.y = tf32r(vk.y);
            vk.z = tf32r(vk.z); vk.w = tf32r(vk.w);
            *(float4*)(&Ks[row * APAD + c4]) = vk;
            float4 vv = *(const float4*)(vb + (size_t)(t0 + row) * QKV_SSTRIDE + c4);
            vv.x = tf32r(vv.x); vv.y = tf32r(vv.y);
            vv.z = tf32r(vv.z); vv.w = tf32r(vv.w);
            *(float4*)(&Vs[row * APAD + c4]) = vv;
        }
        __syncthreads();

        // S = Q K^T
        float sacc[4][4];
#pragma unroll
        for (int nt = 0; nt < 4; nt++)
#pragma unroll
            for (int c = 0; c < 4; c++) sacc[nt][c] = 0.f;
#pragma unroll
        for (int ks = 0; ks < 64; ks += 8) {
            uint32_t a0 = __float_as_uint(Qs[(wm + gr    ) * APAD + ks + tig    ]);
            uint32_t a1 = __float_as_uint(Qs[(wm + gr + 8) * APAD + ks + tig    ]);
            uint32_t a2 = __float_as_uint(Qs[(wm + gr    ) * APAD + ks + tig + 4]);
            uint32_t a3 = __float_as_uint(Qs[(wm + gr + 8) * APAD + ks + tig + 4]);
#pragma unroll
            for (int nt = 0; nt < 4; nt++) {
                int cc = wn + nt * 8;
                uint32_t b0 = __float_as_uint(Ks[(cc + gr) * APAD + ks + tig    ]);
                uint32_t b1 = __float_as_uint(Ks[(cc + gr) * APAD + ks + tig + 4]);
                mma_tf32(sacc[nt][0], sacc[nt][1], sacc[nt][2], sacc[nt][3],
                         a0, a1, a2, a3, b0, b1);
            }
        }
        // (S + mask) * 1/sqrt(K) -> Ps
#pragma unroll
        for (int nt = 0; nt < 4; nt++) {
            int col = wn + nt * 8 + 2 * tig;
#pragma unroll
            for (int h = 0; h < 2; h++) {
                int r = wm + gr + h * 8;
                const float2 mv = *(const float2*)(mask + (size_t)(s0 + r) * SEQ + t0 + col);
                Ps[r * APAD + col    ] = (sacc[nt][h * 2 + 0] + mv.x) * 0.125f;
                Ps[r * APAD + col + 1] = (sacc[nt][h * 2 + 1] + mv.y) * 0.125f;
            }
        }
        __syncthreads();

        // online softmax: 4 threads per row
        {
            int row  = tid >> 2;
            int part = tid & 3;
            float tm = -1e30f;
#pragma unroll
            for (int j = part * 16; j < part * 16 + 16; j++)
                tm = fmaxf(tm, Ps[row * APAD + j]);
            tm = fmaxf(tm, __shfl_xor_sync(0xffffffffu, tm, 1));
            tm = fmaxf(tm, __shfl_xor_sync(0xffffffffu, tm, 2));
            float old_m = rm[row];
            float new_m = fmaxf(old_m, tm);
            float sum = 0.f;
#pragma unroll
            for (int j = part * 16; j < part * 16 + 16; j++) {
                float e = __expf(Ps[row * APAD + j] - new_m);
                Ps[row * APAD + j] = tf32r(e);
                sum += e;
            }
            sum += __shfl_xor_sync(0xffffffffu, sum, 1);
            sum += __shfl_xor_sync(0xffffffffu, sum, 2);
            if (part == 0) {
                float corr = __expf(old_m - new_m);
                rl[row] = rl[row] * corr + sum;
                rm[row] = new_m;
                rc[row] = corr;
            }
        }
        __syncthreads();

        // O = O*corr + P @ V
        float c_lo = rc[wm + gr];
        float c_hi = rc[wm + gr + 8];
#pragma unroll
        for (int nt = 0; nt < 4; nt++) {
            oacc[nt][0] *= c_lo; oacc[nt][1] *= c_lo;
            oacc[nt][2] *= c_hi; oacc[nt][3] *= c_hi;
        }
#pragma unroll
        for (int ks = 0; ks < 64; ks += 8) {
            uint32_t a0 = __float_as_uint(Ps[(wm + gr    ) * APAD + ks + tig    ]);
            uint32_t a1 = __float_as_uint(Ps[(wm + gr + 8) * APAD + ks + tig    ]);
            uint32_t a2 = __float_as_uint(Ps[(wm + gr    ) * APAD + ks + tig + 4]);
            uint32_t a3 = __float_as_uint(Ps[(wm + gr + 8) * APAD + ks + tig + 4]);
#pragma unroll
            for (int nt = 0; nt < 4; nt++) {
                int cc = wn + nt * 8;
                uint32_t b0 = __float_as_uint(Vs[(ks + tig    ) * APAD + cc + gr]);
                uint32_t b1 = __float_as_uint(Vs[(ks + tig + 4) * APAD + cc + gr]);
                mma_tf32(oacc[nt][0], oacc[nt][1], oacc[nt][2], oacc[nt][3],
                         a0, a1, a2, a3, b0, b1);
            }
        }
    }

    // final normalize + store
    {
        float inv_lo = 1.f / rl[wm + gr];
        float inv_hi = 1.f / rl[wm + gr + 8];
#pragma unroll
        for (int nt = 0; nt < 4; nt++) {
            int col = wn + nt * 8 + 2 * tig;
            float2 o0; o0.x = oacc[nt][0] * inv_lo; o0.y = oacc[nt][1] * inv_lo;
            *(float2*)(u + (size_t)(s0 + wm + gr) * 4096 + (size_t)n * 64 + col) = o0;
            float2 o1; o1.x = oacc[nt][2] * inv_hi; o1.y = oacc[nt][3] * inv_hi;
            *(float2*)(u + (size_t)(s0 + wm + gr + 8) * 4096 + (size_t)n * 64 + col) = o1;
        }
    }
}

// ---------------------------------------------------------------------------
// LayerNorm over last dim (1024), one block per row.
// ---------------------------------------------------------------------------
__global__ __launch_bounds__(256) void ln_kernel(
    const float* __restrict__ in, const float* __restrict__ g,
    const float* __restrict__ be, float* __restrict__ out)
{
    const int row = blockIdx.x;
    const int tid = threadIdx.x;
    __shared__ float red[8];
    __shared__ float s_mu, s_rstd;

    float4 v = *(const float4*)(in + (size_t)row * DMODEL + tid * 4);
    float s = v.x + v.y + v.z + v.w;
#pragma unroll
    for (int o = 16; o > 0; o >>= 1) s += __shfl_xor_sync(0xffffffffu, s, o);
    if ((tid & 31) == 0) red[tid >> 5] = s;
    __syncthreads();
    if (tid < 8) {
        float t = red[tid];
#pragma unroll
        for (int o = 4; o > 0; o >>= 1) t += __shfl_xor_sync(0xffu, t, o);
        if (tid == 0) s_mu = t * (1.f / DMODEL);
    }
    __syncthreads();
    float mu = s_mu;
    float d0 = v.x - mu, d1 = v.y - mu, d2 = v.z - mu, d3 = v.w - mu;
    float s2 = d0 * d0 + d1 * d1 + d2 * d2 + d3 * d3;
#pragma unroll
    for (int o = 16; o > 0; o >>= 1) s2 += __shfl_xor_sync(0xffffffffu, s2, o);
    if ((tid & 31) == 0) red[tid >> 5] = s2;
    __syncthreads();
    if (tid < 8) {
        float t = red[tid];
#pragma unroll
        for (int o = 4; o > 0; o >>= 1) t += __shfl_xor_sync(0xffu, t, o);
        if (tid == 0) s_rstd = rsqrtf(t * (1.f / DMODEL) + LN_EPS);
    }
    __syncthreads();
    float rstd = s_rstd;
    float4 gv = *(const float4*)(g + tid * 4);
    float4 bv = *(const float4*)(be + tid * 4);
    float4 ov;
    ov.x = d0 * rstd * gv.x + bv.x;
    ov.y = d1 * rstd * gv.y + bv.y;
    ov.z = d2 * rstd * gv.z + bv.z;
    ov.w = d3 * rstd * gv.w + bv.w;
    *(float4*)(out + (size_t)row * DMODEL + tid * 4) = ov;
}

// ---------------------------------------------------------------------------
extern "C" void kernel_launch(void* const* d_in, const int* in_sizes, int n_in,
                              void* d_out, int out_size)
{
    const float* x    = (const float*)d_in[0];
    const float* mask = (const float*)d_in[1];
    const float* Wq   = (const float*)d_in[2];
    const float* Wk   = (const float*)d_in[3];
    const float* Wv   = (const float*)d_in[4];
    const float* Wc   = (const float*)d_in[5];
    const float* W1   = (const float*)d_in[6];
    const float* b1   = (const float*)d_in[7];
    const float* W2   = (const float*)d_in[8];
    const float* b2   = (const float*)d_in[9];
    const float* g1   = (const float*)d_in[10];
    const float* be1  = (const float*)d_in[11];
    const float* g2   = (const float*)d_in[12];
    const float* be2  = (const float*)d_in[13];
    float* out = (float*)d_out;

    float *qkv, *wp, *u, *t1, *t2, *t3, *hid;
    cudaGetSymbolAddress((void**)&qkv, g_qkv);
    cudaGetSymbolAddress((void**)&wp,  g_wp);
    cudaGetSymbolAddress((void**)&u,   g_u);
    cudaGetSymbolAddress((void**)&t1,  g_t1);
    cudaGetSymbolAddress((void**)&t2,  g_t2);
    cudaGetSymbolAddress((void**)&t3,  g_t3);
    cudaGetSymbolAddress((void**)&hid, g_hid);

    const int attn_smem = ATTN_SMEM_FLOATS * sizeof(float);
    cudaFuncSetAttribute(attn_tc, cudaFuncAttributeMaxDynamicSharedMemorySize, attn_smem);
    cudaFuncSetAttribute(gemm_tc, cudaFuncAttributeMaxDynamicSharedMemorySize, GEMM_SMEM_BYTES);

    dim3 blk(256);

    // pack QKV weights, fused projection -> qkv [8192, 3072]
    pack_qkv<<<3072, blk>>>(Wq, Wk, Wv, wp);
    gemm_tc<<<dim3(3072 / 128, MROWS / 128), blk, GEMM_SMEM_BYTES>>>(
        x, wp, nullptr, nullptr, qkv, 3072, DMODEL, 0);

    // attention -> u
    attn_tc<<<dim3(SEQ / 64, 64), blk, attn_smem>>>(qkv, mask, u);

    // x + u @ Wc^T -> t1;  LN1 -> t2
    gemm_tc<<<dim3(DMODEL / 128, MROWS / 128), blk, GEMM_SMEM_BYTES>>>(
        u, Wc, nullptr, x, t1, DMODEL, DMODEL, 3);
    ln_kernel<<<MROWS, blk>>>(t1, g1, be1, t2);

    // FFN: relu(t2@W1^T+b1) -> hid;  hid@W2^T+b2 + t2 -> t3;  LN2 -> out
    gemm_tc<<<dim3(FFDIM / 128, MROWS / 128), blk, GEMM_SMEM_BYTES>>>(
        t2, W1, b1, nullptr, hid, FFDIM, DMODEL, 1);
    gemm_tc<<<dim3(DMODEL / 128, MROWS / 128), blk, GEMM_SMEM_BYTES>>>(
        hid, W2, b2, t2, t3, DMODEL, FFDIM, 2);
    ln_kernel<<<MROWS, blk>>>(t3, g2, be2, out);
}

// round 6
// speedup vs baseline: 3.2213x; 1.0461x over previous
#include <cuda_runtime.h>
#include <math.h>
#include <stdint.h>

// ---------------------------------------------------------------------------
// PTransformerBlock: S=2048 B=4 D=1024 H=16 K=64 FF=4096.
// Round 6: GEMM inner loop on ldmatrix (LDSM) + 3-stage cp.async pipeline.
// ---------------------------------------------------------------------------

#define SEQ   2048
#define BATCH 4
#define DMODEL 1024
#define FFDIM 4096
#define MROWS (SEQ*BATCH)   // 8192
#define LN_EPS 1e-5f

// scratch (allocation-free: device globals)
__device__ float g_qkv[MROWS * 3072];
__device__ float g_wp [3072 * DMODEL];
__device__ float g_u  [MROWS * DMODEL];
__device__ float g_t1 [MROWS * DMODEL];
__device__ float g_t2 [MROWS * DMODEL];
__device__ float g_t3 [MROWS * DMODEL];
__device__ float g_hid[MROWS * FFDIM];

__device__ __forceinline__ float tf32r(float x) {
    uint32_t u;
    asm("cvt.rna.tf32.f32 %0, %1;" : "=r"(u) : "f"(x));
    return __uint_as_float(u);
}

__device__ __forceinline__ void mma_tf32(
    float& d0, float& d1, float& d2, float& d3,
    uint32_t a0, uint32_t a1, uint32_t a2, uint32_t a3,
    uint32_t b0, uint32_t b1)
{
    asm volatile(
        "mma.sync.aligned.m16n8k8.row.col.f32.tf32.tf32.f32 "
        "{%0,%1,%2,%3}, {%4,%5,%6,%7}, {%8,%9}, {%0,%1,%2,%3};"
        : "+f"(d0), "+f"(d1), "+f"(d2), "+f"(d3)
        : "r"(a0), "r"(a1), "r"(a2), "r"(a3), "r"(b0), "r"(b1));
}

__device__ __forceinline__ void ldsm4(
    uint32_t& r0, uint32_t& r1, uint32_t& r2, uint32_t& r3, uint32_t addr)
{
    asm volatile("ldmatrix.sync.aligned.m8n8.x4.shared.b16 {%0,%1,%2,%3}, [%4];"
                 : "=r"(r0), "=r"(r1), "=r"(r2), "=r"(r3) : "r"(addr));
}

__device__ __forceinline__ void cp16(uint32_t s, const float* g) {
    asm volatile("cp.async.cg.shared.global [%0], [%1], 16;" :: "r"(s), "l"(g));
}
__device__ __forceinline__ uint32_t saddr(const void* p) {
    return (uint32_t)__cvta_generic_to_shared(p);
}

// ---------------------------------------------------------------------------
// TF32 tensor-core GEMM, 3-stage cp.async pipeline, ldmatrix fragment loads.
// C[M,N] = A[M,Kd] * W[N,Kd]^T (+ epilogue)
// Block tile 128x128, BK=32, 256 threads = 8 warps of 64x32 warp tiles.
// fp32 raw in smem; mma reads tf32 bits (implicit truncation).
// EPI: 0=none  1=+bias,relu  2=+bias,+res  3=+res
// ---------------------------------------------------------------------------
#define PADK 36
#define STG  (128 * PADK)                      // floats per matrix per stage
#define NSTAGE 3
#define GEMM_SMEM_BYTES (NSTAGE * 2 * STG * 4) // 110592

__global__ __launch_bounds__(256) void gemm_tc(
    const float* __restrict__ A, const float* __restrict__ W,
    const float* __restrict__ bias, const float* __restrict__ res,
    float* __restrict__ C, int N, int Kd, int EPI)
{
    extern __shared__ float smem[];

    const int tid  = threadIdx.x;
    const int warp = tid >> 5;
    const int lane = tid & 31;
    const int gr   = lane >> 2;
    const int tig  = lane & 3;
    const int wm   = (warp & 1) * 64;
    const int wn   = (warp >> 1) * 32;
    const int m0   = blockIdx.y * 128;
    const int n0   = blockIdx.x * 128;

    const uint32_t sb = saddr(smem);
    // ldmatrix per-thread row addresses (byte offsets within a stage matrix)
    // A x4: tiles (rows 0-7,k0)(rows 8-15,k0)(rows 0-7,k4)(rows 8-15,k4)
    const uint32_t aoff = ((wm + (lane & 15)) * PADK + ((lane >> 4) << 2)) << 2;
    // B x4 pair: tiles (n 0-7,k0)(n 0-7,k4)(n 8-15,k0)(n 8-15,k4)
    const uint32_t boff = ((wn + ((lane >> 4) << 3) + (lane & 7)) * PADK
                           + (((lane >> 3) & 1) << 2)) << 2;

    // loader offsets
    const int lrow = tid >> 3;
    const int lc4  = (tid & 7) * 4;

    float acc[4][4][4];
#pragma unroll
    for (int mt = 0; mt < 4; mt++)
#pragma unroll
        for (int nt = 0; nt < 4; nt++)
#pragma unroll
            for (int c = 0; c < 4; c++) acc[mt][nt][c] = 0.f;

    const int ktiles = Kd >> 5;

    // prefetch tiles 0 and 1
#pragma unroll
    for (int pf = 0; pf < 2; pf++) {
        float* As_ = smem + (size_t)pf * 2 * STG;
        float* Bs_ = As_ + STG;
        const int k0 = pf << 5;
#pragma unroll
        for (int it = 0; it < 4; it++) {
            int row = lrow + it * 32;
            cp16(saddr(As_ + row * PADK + lc4), A + (size_t)(m0 + row) * Kd + k0 + lc4);
            cp16(saddr(Bs_ + row * PADK + lc4), W + (size_t)(n0 + row) * Kd + k0 + lc4);
        }
        asm volatile("cp.async.commit_group;");
    }

    for (int t = 0; t < ktiles; t++) {
        if (t + 2 < ktiles) {
            __syncthreads();   // all warps done with stage (t+2)%3 (tile t-1)
            float* As_ = smem + (size_t)((t + 2) % NSTAGE) * 2 * STG;
            float* Bs_ = As_ + STG;
            const int k0 = (t + 2) << 5;
#pragma unroll
            for (int it = 0; it < 4; it++) {
                int row = lrow + it * 32;
                cp16(saddr(As_ + row * PADK + lc4), A + (size_t)(m0 + row) * Kd + k0 + lc4);
                cp16(saddr(Bs_ + row * PADK + lc4), W + (size_t)(n0 + row) * Kd + k0 + lc4);
            }
            asm volatile("cp.async.commit_group;");
        }
        {
            int rem = ktiles - 1 - t;
            if (rem >= 2)      asm volatile("cp.async.wait_group 2;");
            else if (rem == 1) asm volatile("cp.async.wait_group 1;");
            else               asm volatile("cp.async.wait_group 0;");
        }
        __syncthreads();

        const uint32_t stoff = (uint32_t)((t % NSTAGE) * 2 * STG * 4);
        const uint32_t aA = sb + stoff + aoff;
        const uint32_t aB = sb + stoff + (uint32_t)(STG * 4) + boff;

#pragma unroll
        for (int ks = 0; ks < 32; ks += 8) {
            uint32_t a[4][4], b[4][2];
#pragma unroll
            for (int mt = 0; mt < 4; mt++)
                ldsm4(a[mt][0], a[mt][1], a[mt][2], a[mt][3],
                      aA + (uint32_t)(mt * 16 * PADK * 4) + (uint32_t)(ks * 4));
#pragma unroll
            for (int np = 0; np < 2; np++)
                ldsm4(b[2 * np][0], b[2 * np][1], b[2 * np + 1][0], b[2 * np + 1][1],
                      aB + (uint32_t)(np * 16 * PADK * 4) + (uint32_t)(ks * 4));
#pragma unroll
            for (int mt = 0; mt < 4; mt++)
#pragma unroll
                for (int nt = 0; nt < 4; nt++)
                    mma_tf32(acc[mt][nt][0], acc[mt][nt][1], acc[mt][nt][2], acc[mt][nt][3],
                             a[mt][0], a[mt][1], a[mt][2], a[mt][3],
                             b[nt][0], b[nt][1]);
        }
    }

#pragma unroll
    for (int mt = 0; mt < 4; mt++) {
#pragma unroll
        for (int nt = 0; nt < 4; nt++) {
            int row = m0 + wm + mt * 16 + gr;
            int col = n0 + wn + nt * 8 + 2 * tig;
#pragma unroll
            for (int h = 0; h < 2; h++) {
                int r = row + h * 8;
                float c0 = acc[mt][nt][h * 2 + 0];
                float c1 = acc[mt][nt][h * 2 + 1];
                if (EPI == 1) {
                    c0 = fmaxf(c0 + bias[col], 0.f);
                    c1 = fmaxf(c1 + bias[col + 1], 0.f);
                } else if (EPI == 2) {
                    const float2 rv = *(const float2*)(res + (size_t)r * N + col);
                    c0 += bias[col] + rv.x;
                    c1 += bias[col + 1] + rv.y;
                } else if (EPI == 3) {
                    const float2 rv = *(const float2*)(res + (size_t)r * N + col);
                    c0 += rv.x;
                    c1 += rv.y;
                }
                float2 o; o.x = c0; o.y = c1;
                *(float2*)(C + (size_t)r * N + col) = o;
            }
        }
    }
}

// ---------------------------------------------------------------------------
// Pack [Wq; Wk; Wv] -> Wp [3072, 1024]
// ---------------------------------------------------------------------------
__global__ __launch_bounds__(256) void pack_qkv(
    const float* __restrict__ Wq, const float* __restrict__ Wk,
    const float* __restrict__ Wv, float* __restrict__ Wp)
{
    int i = blockIdx.x * blockDim.x + threadIdx.x;     // float4 index
    int row = (i * 4) >> 10;
    int col = (i * 4) & 1023;
    const float* src;
    if (row < 1024)      src = Wq + (size_t)row * 1024 + col;
    else if (row < 2048) src = Wk + (size_t)(row - 1024) * 1024 + col;
    else                 src = Wv + (size_t)(row - 2048) * 1024 + col;
    *(float4*)(Wp + (size_t)i * 4) = *(const float4*)src;
}

// ---------------------------------------------------------------------------
// Tensor-core flash attention on packed qkv [8192, 3072] (unchanged R5).
// ---------------------------------------------------------------------------
#define APAD 68
#define ATTN_SMEM_FLOATS (4*64*APAD + 3*64)
#define QKV_SSTRIDE (4*3072)

__global__ __launch_bounds__(256) void attn_tc(
    const float* __restrict__ qkv, const float* __restrict__ mask,
    float* __restrict__ u)
{
    extern __shared__ float sm[];
    float* Qs = sm;
    float* Ks = Qs + 64 * APAD;
    float* Vs = Ks + 64 * APAD;
    float* Ps = Vs + 64 * APAD;
    float* rm = Ps + 64 * APAD;
    float* rl = rm + 64;
    float* rc = rl + 64;

    const int n   = blockIdx.y;
    const int bb  = n >> 4;
    const int hh  = n & 15;
    const int s0  = blockIdx.x * 64;
    const int tid = threadIdx.x;
    const int warp = tid >> 5;
    const int lane = tid & 31;
    const int gr   = lane >> 2;
    const int tig  = lane & 3;
    const int wm   = (warp & 3) * 16;
    const int wn   = (warp >> 2) * 32;

    const float* qb = qkv + (size_t)bb * 3072 + hh * 64;
    const float* kb = qb + 1024;
    const float* vb = qb + 2048;

#pragma unroll
    for (int it = 0; it < 4; it++) {
        int lin = tid + it * 256;
        int row = lin >> 4;
        int c4  = (lin & 15) * 4;
        float4 vq = *(const float4*)(qb + (size_t)(s0 + row) * QKV_SSTRIDE + c4);
        vq.x = tf32r(vq.x); vq.y = tf32r(vq.y);
        vq.z = tf32r(vq.z); vq.w = tf32r(vq.w);
        *(float4*)(&Qs[row * APAD + c4]) = vq;
    }
    if (tid < 64) { rm[tid] = -1e30f; rl[tid] = 0.f; }

    float oacc[4][4];
#pragma unroll
    for (int nt = 0; nt < 4; nt++)
#pragma unroll
        for (int c = 0; c < 4; c++) oacc[nt][c] = 0.f;

    for (int t0 = 0; t0 < SEQ; t0 += 64) {
        __syncthreads();
#pragma unroll
        for (int it = 0; it < 4; it++) {
            int lin = tid + it * 256;
            int row = lin >> 4;
            int c4  = (lin & 15) * 4;
            float4 vk = *(const float4*)(kb + (size_t)(t0 + row) * QKV_SSTRIDE + c4);
            vk.x = tf32r(vk.x); vk.y = tf32r(vk.y);
            vk.z = tf32r(vk.z); vk.w = tf32r(vk.w);
            *(float4*)(&Ks[row * APAD + c4]) = vk;
            float4 vv = *(const float4*)(vb + (size_t)(t0 + row) * QKV_SSTRIDE + c4);
            vv.x = tf32r(vv.x); vv.y = tf32r(vv.y);
            vv.z = tf32r(vv.z); vv.w = tf32r(vv.w);
            *(float4*)(&Vs[row * APAD + c4]) = vv;
        }
        __syncthreads();

        float sacc[4][4];
#pragma unroll
        for (int nt = 0; nt < 4; nt++)
#pragma unroll
            for (int c = 0; c < 4; c++) sacc[nt][c] = 0.f;
#pragma unroll
        for (int ks = 0; ks < 64; ks += 8) {
            uint32_t a0 = __float_as_uint(Qs[(wm + gr    ) * APAD + ks + tig    ]);
            uint32_t a1 = __float_as_uint(Qs[(wm + gr + 8) * APAD + ks + tig    ]);
            uint32_t a2 = __float_as_uint(Qs[(wm + gr    ) * APAD + ks + tig + 4]);
            uint32_t a3 = __float_as_uint(Qs[(wm + gr + 8) * APAD + ks + tig + 4]);
#pragma unroll
            for (int nt = 0; nt < 4; nt++) {
                int cc = wn + nt * 8;
                uint32_t b0 = __float_as_uint(Ks[(cc + gr) * APAD + ks + tig    ]);
                uint32_t b1 = __float_as_uint(Ks[(cc + gr) * APAD + ks + tig + 4]);
                mma_tf32(sacc[nt][0], sacc[nt][1], sacc[nt][2], sacc[nt][3],
                         a0, a1, a2, a3, b0, b1);
            }
        }
#pragma unroll
        for (int nt = 0; nt < 4; nt++) {
            int col = wn + nt * 8 + 2 * tig;
#pragma unroll
            for (int h = 0; h < 2; h++) {
                int r = wm + gr + h * 8;
                const float2 mv = *(const float2*)(mask + (size_t)(s0 + r) * SEQ + t0 + col);
                Ps[r * APAD + col    ] = (sacc[nt][h * 2 + 0] + mv.x) * 0.125f;
                Ps[r * APAD + col + 1] = (sacc[nt][h * 2 + 1] + mv.y) * 0.125f;
            }
        }
        __syncthreads();

        {
            int row  = tid >> 2;
            int part = tid & 3;
            float tm = -1e30f;
#pragma unroll
            for (int j = part * 16; j < part * 16 + 16; j++)
                tm = fmaxf(tm, Ps[row * APAD + j]);
            tm = fmaxf(tm, __shfl_xor_sync(0xffffffffu, tm, 1));
            tm = fmaxf(tm, __shfl_xor_sync(0xffffffffu, tm, 2));
            float old_m = rm[row];
            float new_m = fmaxf(old_m, tm);
            float sum = 0.f;
#pragma unroll
            for (int j = part * 16; j < part * 16 + 16; j++) {
                float e = __expf(Ps[row * APAD + j] - new_m);
                Ps[row * APAD + j] = tf32r(e);
                sum += e;
            }
            sum += __shfl_xor_sync(0xffffffffu, sum, 1);
            sum += __shfl_xor_sync(0xffffffffu, sum, 2);
            if (part == 0) {
                float corr = __expf(old_m - new_m);
                rl[row] = rl[row] * corr + sum;
                rm[row] = new_m;
                rc[row] = corr;
            }
        }
        __syncthreads();

        float c_lo = rc[wm + gr];
        float c_hi = rc[wm + gr + 8];
#pragma unroll
        for (int nt = 0; nt < 4; nt++) {
            oacc[nt][0] *= c_lo; oacc[nt][1] *= c_lo;
            oacc[nt][2] *= c_hi; oacc[nt][3] *= c_hi;
        }
#pragma unroll
        for (int ks = 0; ks < 64; ks += 8) {
            uint32_t a0 = __float_as_uint(Ps[(wm + gr    ) * APAD + ks + tig    ]);
            uint32_t a1 = __float_as_uint(Ps[(wm + gr + 8) * APAD + ks + tig    ]);
            uint32_t a2 = __float_as_uint(Ps[(wm + gr    ) * APAD + ks + tig + 4]);
            uint32_t a3 = __float_as_uint(Ps[(wm + gr + 8) * APAD + ks + tig + 4]);
#pragma unroll
            for (int nt = 0; nt < 4; nt++) {
                int cc = wn + nt * 8;
                uint32_t b0 = __float_as_uint(Vs[(ks + tig    ) * APAD + cc + gr]);
                uint32_t b1 = __float_as_uint(Vs[(ks + tig + 4) * APAD + cc + gr]);
                mma_tf32(oacc[nt][0], oacc[nt][1], oacc[nt][2], oacc[nt][3],
                         a0, a1, a2, a3, b0, b1);
            }
        }
    }

    {
        float inv_lo = 1.f / rl[wm + gr];
        float inv_hi = 1.f / rl[wm + gr + 8];
#pragma unroll
        for (int nt = 0; nt < 4; nt++) {
            int col = wn + nt * 8 + 2 * tig;
            float2 o0; o0.x = oacc[nt][0] * inv_lo; o0.y = oacc[nt][1] * inv_lo;
            *(float2*)(u + (size_t)(s0 + wm + gr) * 4096 + (size_t)n * 64 + col) = o0;
            float2 o1; o1.x = oacc[nt][2] * inv_hi; o1.y = oacc[nt][3] * inv_hi;
            *(float2*)(u + (size_t)(s0 + wm + gr + 8) * 4096 + (size_t)n * 64 + col) = o1;
        }
    }
}

// ---------------------------------------------------------------------------
// LayerNorm over last dim (1024), one block per row.
// ---------------------------------------------------------------------------
__global__ __launch_bounds__(256) void ln_kernel(
    const float* __restrict__ in, const float* __restrict__ g,
    const float* __restrict__ be, float* __restrict__ out)
{
    const int row = blockIdx.x;
    const int tid = threadIdx.x;
    __shared__ float red[8];
    __shared__ float s_mu, s_rstd;

    float4 v = *(const float4*)(in + (size_t)row * DMODEL + tid * 4);
    float s = v.x + v.y + v.z + v.w;
#pragma unroll
    for (int o = 16; o > 0; o >>= 1) s += __shfl_xor_sync(0xffffffffu, s, o);
    if ((tid & 31) == 0) red[tid >> 5] = s;
    __syncthreads();
    if (tid < 8) {
        float t = red[tid];
#pragma unroll
        for (int o = 4; o > 0; o >>= 1) t += __shfl_xor_sync(0xffu, t, o);
        if (tid == 0) s_mu = t * (1.f / DMODEL);
    }
    __syncthreads();
    float mu = s_mu;
    float d0 = v.x - mu, d1 = v.y - mu, d2 = v.z - mu, d3 = v.w - mu;
    float s2 = d0 * d0 + d1 * d1 + d2 * d2 + d3 * d3;
#pragma unroll
    for (int o = 16; o > 0; o >>= 1) s2 += __shfl_xor_sync(0xffffffffu, s2, o);
    if ((tid & 31) == 0) red[tid >> 5] = s2;
    __syncthreads();
    if (tid < 8) {
        float t = red[tid];
#pragma unroll
        for (int o = 4; o > 0; o >>= 1) t += __shfl_xor_sync(0xffu, t, o);
        if (tid == 0) s_rstd = rsqrtf(t * (1.f / DMODEL) + LN_EPS);
    }
    __syncthreads();
    float rstd = s_rstd;
    float4 gv = *(const float4*)(g + tid * 4);
    float4 bv = *(const float4*)(be + tid * 4);
    float4 ov;
    ov.x = d0 * rstd * gv.x + bv.x;
    ov.y = d1 * rstd * gv.y + bv.y;
    ov.z = d2 * rstd * gv.z + bv.z;
    ov.w = d3 * rstd * gv.w + bv.w;
    *(float4*)(out + (size_t)row * DMODEL + tid * 4) = ov;
}

// ---------------------------------------------------------------------------
extern "C" void kernel_launch(void* const* d_in, const int* in_sizes, int n_in,
                              void* d_out, int out_size)
{
    const float* x    = (const float*)d_in[0];
    const float* mask = (const float*)d_in[1];
    const float* Wq   = (const float*)d_in[2];
    const float* Wk   = (const float*)d_in[3];
    const float* Wv   = (const float*)d_in[4];
    const float* Wc   = (const float*)d_in[5];
    const float* W1   = (const float*)d_in[6];
    const float* b1   = (const float*)d_in[7];
    const float* W2   = (const float*)d_in[8];
    const float* b2   = (const float*)d_in[9];
    const float* g1   = (const float*)d_in[10];
    const float* be1  = (const float*)d_in[11];
    const float* g2   = (const float*)d_in[12];
    const float* be2  = (const float*)d_in[13];
    float* out = (float*)d_out;

    float *qkv, *wp, *u, *t1, *t2, *t3, *hid;
    cudaGetSymbolAddress((void**)&qkv, g_qkv);
    cudaGetSymbolAddress((void**)&wp,  g_wp);
    cudaGetSymbolAddress((void**)&u,   g_u);
    cudaGetSymbolAddress((void**)&t1,  g_t1);
    cudaGetSymbolAddress((void**)&t2,  g_t2);
    cudaGetSymbolAddress((void**)&t3,  g_t3);
    cudaGetSymbolAddress((void**)&hid, g_hid);

    const int attn_smem = ATTN_SMEM_FLOATS * sizeof(float);
    cudaFuncSetAttribute(attn_tc, cudaFuncAttributeMaxDynamicSharedMemorySize, attn_smem);
    cudaFuncSetAttribute(gemm_tc, cudaFuncAttributeMaxDynamicSharedMemorySize, GEMM_SMEM_BYTES);

    dim3 blk(256);

    // pack QKV weights, fused projection -> qkv [8192, 3072]
    pack_qkv<<<3072, blk>>>(Wq, Wk, Wv, wp);
    gemm_tc<<<dim3(3072 / 128, MROWS / 128), blk, GEMM_SMEM_BYTES>>>(
        x, wp, nullptr, nullptr, qkv, 3072, DMODEL, 0);

    // attention -> u
    attn_tc<<<dim3(SEQ / 64, 64), blk, attn_smem>>>(qkv, mask, u);

    // x + u @ Wc^T -> t1;  LN1 -> t2
    gemm_tc<<<dim3(DMODEL / 128, MROWS / 128), blk, GEMM_SMEM_BYTES>>>(
        u, Wc, nullptr, x, t1, DMODEL, DMODEL, 3);
    ln_kernel<<<MROWS, blk>>>(t1, g1, be1, t2);

    // FFN: relu(t2@W1^T+b1) -> hid;  hid@W2^T+b2 + t2 -> t3;  LN2 -> out
    gemm_tc<<<dim3(FFDIM / 128, MROWS / 128), blk, GEMM_SMEM_BYTES>>>(
        t2, W1, b1, nullptr, hid, FFDIM, DMODEL, 1);
    gemm_tc<<<dim3(DMODEL / 128, MROWS / 128), blk, GEMM_SMEM_BYTES>>>(
        hid, W2, b2, t2, t3, DMODEL, FFDIM, 2);
    ln_kernel<<<MROWS, blk>>>(t3, g2, be2, out);
}

// round 8
// speedup vs baseline: 4.6744x; 1.4511x over previous
#include <cuda_runtime.h>
#include <cuda_fp16.h>
#include <math.h>
#include <stdint.h>

// ---------------------------------------------------------------------------
// PTransformerBlock: S=2048 B=4 D=1024 H=16 K=64 FF=4096.
// Round 8: fp16 mma.sync m16n8k16 GEMMs (2x tf32 throughput, same mantissa),
//          SW128-swizzled smem, 3-stage cp.async, fp16 inter-GEMM tensors.
//          (tcgen05 unavailable: harness targets sm_100, not sm_100a.)
// ---------------------------------------------------------------------------

#define SEQ   2048
#define BATCH 4
#define DMODEL 1024
#define FFDIM 4096
#define MROWS (SEQ*BATCH)   // 8192
#define LN_EPS 1e-5f

// scratch (allocation-free: device globals)
__device__ __half g_xh  [MROWS * DMODEL];
__device__ __half g_wph [3072 * DMODEL];
__device__ __half g_wch [DMODEL * DMODEL];
__device__ __half g_w1h [FFDIM * DMODEL];
__device__ __half g_w2h [DMODEL * FFDIM];
__device__ __half g_qkvh[MROWS * 3072];
__device__ __half g_uh  [MROWS * DMODEL];
__device__ __half g_t2h [MROWS * DMODEL];
__device__ __half g_hidh[MROWS * FFDIM];
__device__ float  g_t1  [MROWS * DMODEL];
__device__ float  g_t2  [MROWS * DMODEL];
__device__ float  g_t3  [MROWS * DMODEL];

__device__ __forceinline__ float tf32r(float x) {
    uint32_t u;
    asm("cvt.rna.tf32.f32 %0, %1;" : "=r"(u) : "f"(x));
    return __uint_as_float(u);
}

__device__ __forceinline__ void mma_tf32(
    float& d0, float& d1, float& d2, float& d3,
    uint32_t a0, uint32_t a1, uint32_t a2, uint32_t a3,
    uint32_t b0, uint32_t b1)
{
    asm volatile(
        "mma.sync.aligned.m16n8k8.row.col.f32.tf32.tf32.f32 "
        "{%0,%1,%2,%3}, {%4,%5,%6,%7}, {%8,%9}, {%0,%1,%2,%3};"
        : "+f"(d0), "+f"(d1), "+f"(d2), "+f"(d3)
        : "r"(a0), "r"(a1), "r"(a2), "r"(a3), "r"(b0), "r"(b1));
}

__device__ __forceinline__ void mma_f16(
    float& d0, float& d1, float& d2, float& d3,
    uint32_t a0, uint32_t a1, uint32_t a2, uint32_t a3,
    uint32_t b0, uint32_t b1)
{
    asm volatile(
        "mma.sync.aligned.m16n8k16.row.col.f32.f16.f16.f32 "
        "{%0,%1,%2,%3}, {%4,%5,%6,%7}, {%8,%9}, {%0,%1,%2,%3};"
        : "+f"(d0), "+f"(d1), "+f"(d2), "+f"(d3)
        : "r"(a0), "r"(a1), "r"(a2), "r"(a3), "r"(b0), "r"(b1));
}

__device__ __forceinline__ void ldsm4(
    uint32_t& r0, uint32_t& r1, uint32_t& r2, uint32_t& r3, uint32_t addr)
{
    asm volatile("ldmatrix.sync.aligned.m8n8.x4.shared.b16 {%0,%1,%2,%3}, [%4];"
                 : "=r"(r0), "=r"(r1), "=r"(r2), "=r"(r3) : "r"(addr));
}

__device__ __forceinline__ void cp16(uint32_t s, const void* g) {
    asm volatile("cp.async.cg.shared.global [%0], [%1], 16;" :: "r"(s), "l"(g));
}
__device__ __forceinline__ uint32_t saddr(const void* p) {
    return (uint32_t)__cvta_generic_to_shared(p);
}
#define SWZ128(o) ((o) ^ (((o) >> 3) & 0x70))

// ---------------------------------------------------------------------------
// fp16 tensor-core GEMM: C[M,N] = A[M,Kd] * W[N,Kd]^T (+ epilogue)
// Block tile 128x128, BK=64 halves, 256 threads = 8 warps of 64x32 tiles.
// SW128-swizzled smem (128B rows), ldmatrix fragments, 3-stage cp.async.
// EPI: 0=none,out fp16  1=+bias,relu,out fp16  2=+bias,+res,out f32  3=+res,out f32
// ---------------------------------------------------------------------------
#define STAGE_BYTES 32768                   // A 16KB + B 16KB
#define NSTAGE 3
#define GEMM_SMEM_BYTES (NSTAGE * STAGE_BYTES)   // 98304

__device__ __forceinline__ void load_tile_h(
    uint32_t base, const __half* __restrict__ A, const __half* __restrict__ W,
    int m0, int n0, int Kd, int k0, int tid)
{
#pragma unroll
    for (int it = 0; it < 4; it++) {
        int lin = tid + it * 256;          // 0..1023
        int row = lin >> 3;                // 0..127
        int ch  = lin & 7;                 // 16B chunk (8 halves)
        uint32_t off = (uint32_t)(row * 128 + ch * 16);
        uint32_t sw  = SWZ128(off);
        cp16(base + sw,         A + (size_t)(m0 + row) * Kd + k0 + ch * 8);
        cp16(base + 16384 + sw, W + (size_t)(n0 + row) * Kd + k0 + ch * 8);
    }
}

__global__ __launch_bounds__(256, 2) void gemm_h(
    const __half* __restrict__ A, const __half* __restrict__ W,
    const float* __restrict__ bias, const float* __restrict__ res,
    void* __restrict__ Cv, int N, int Kd, int EPI)
{
    extern __shared__ __align__(1024) char smem[];

    const int tid  = threadIdx.x;
    const int warp = tid >> 5;
    const int lane = tid & 31;
    const int gr   = lane >> 2;
    const int tig  = lane & 3;
    const int wm   = (warp & 1) * 64;
    const int wn   = (warp >> 1) * 32;
    const int m0   = blockIdx.y * 128;
    const int n0   = blockIdx.x * 128;

    const uint32_t sb = saddr(smem);

    float acc[4][4][4];
#pragma unroll
    for (int mt = 0; mt < 4; mt++)
#pragma unroll
        for (int nt = 0; nt < 4; nt++)
#pragma unroll
            for (int c = 0; c < 4; c++) acc[mt][nt][c] = 0.f;

    const int ktiles = Kd >> 6;

    // prologue: tiles 0..2
#pragma unroll
    for (int pf = 0; pf < NSTAGE; pf++) {
        load_tile_h(sb + pf * STAGE_BYTES, A, W, m0, n0, Kd, pf * 64, tid);
        asm volatile("cp.async.commit_group;");
    }

    for (int t = 0; t < ktiles; t++) {
        {
            int rem = ktiles - 1 - t;
            if (rem >= 2)      asm volatile("cp.async.wait_group 2;");
            else if (rem == 1) asm volatile("cp.async.wait_group 1;");
            else               asm volatile("cp.async.wait_group 0;");
        }
        __syncthreads();

        const uint32_t sA = sb + (uint32_t)((t % NSTAGE) * STAGE_BYTES);
        const uint32_t sB = sA + 16384u;

#pragma unroll
        for (int ks = 0; ks < 4; ks++) {         // k16 steps within BK=64
            uint32_t a[4][4], b[4][2];
#pragma unroll
            for (int mt = 0; mt < 4; mt++) {
                uint32_t off = (uint32_t)((wm + mt * 16 + (lane & 15)) * 128
                                          + ks * 32 + ((lane >> 4) << 4));
                ldsm4(a[mt][0], a[mt][1], a[mt][2], a[mt][3], sA + SWZ128(off));
            }
#pragma unroll
            for (int np = 0; np < 2; np++) {
                uint32_t off = (uint32_t)((wn + np * 16 + (lane & 7)
                                           + ((lane >> 4) & 1) * 8) * 128
                                          + ks * 32 + (((lane >> 3) & 1) << 4));
                ldsm4(b[2 * np][0], b[2 * np][1], b[2 * np + 1][0], b[2 * np + 1][1],
                      sB + SWZ128(off));
            }
#pragma unroll
            for (int mt = 0; mt < 4; mt++)
#pragma unroll
                for (int nt = 0; nt < 4; nt++)
                    mma_f16(acc[mt][nt][0], acc[mt][nt][1], acc[mt][nt][2], acc[mt][nt][3],
                            a[mt][0], a[mt][1], a[mt][2], a[mt][3],
                            b[nt][0], b[nt][1]);
        }
        __syncthreads();

        if (t + NSTAGE < ktiles) {
            load_tile_h(sA, A, W, m0, n0, Kd, (t + NSTAGE) * 64, tid);
            asm volatile("cp.async.commit_group;");
        }
    }

    // epilogue
#pragma unroll
    for (int mt = 0; mt < 4; mt++) {
#pragma unroll
        for (int nt = 0; nt < 4; nt++) {
            int row = m0 + wm + mt * 16 + gr;
            int col = n0 + wn + nt * 8 + 2 * tig;
#pragma unroll
            for (int h = 0; h < 2; h++) {
                int r = row + h * 8;
                float c0 = acc[mt][nt][h * 2 + 0];
                float c1 = acc[mt][nt][h * 2 + 1];
                if (EPI == 0) {
                    *(__half2*)((__half*)Cv + (size_t)r * N + col) =
                        __floats2half2_rn(c0, c1);
                } else if (EPI == 1) {
                    c0 = fmaxf(c0 + bias[col], 0.f);
                    c1 = fmaxf(c1 + bias[col + 1], 0.f);
                    *(__half2*)((__half*)Cv + (size_t)r * N + col) =
                        __floats2half2_rn(c0, c1);
                } else if (EPI == 2) {
                    const float2 rv = *(const float2*)(res + (size_t)r * N + col);
                    float2 o; o.x = c0 + bias[col] + rv.x; o.y = c1 + bias[col + 1] + rv.y;
                    *(float2*)((float*)Cv + (size_t)r * N + col) = o;
                } else {
                    const float2 rv = *(const float2*)(res + (size_t)r * N + col);
                    float2 o; o.x = c0 + rv.x; o.y = c1 + rv.y;
                    *(float2*)((float*)Cv + (size_t)r * N + col) = o;
                }
            }
        }
    }
}

// ---------------------------------------------------------------------------
// f32 -> fp16 converters
// ---------------------------------------------------------------------------
__global__ __launch_bounds__(256) void cvt_h(
    const float* __restrict__ in, __half* __restrict__ out)
{
    int i = blockIdx.x * blockDim.x + threadIdx.x;     // float4 index
    float4 v = ((const float4*)in)[i];
    __half2 h0 = __floats2half2_rn(v.x, v.y);
    __half2 h1 = __floats2half2_rn(v.z, v.w);
    ((__half2*)out)[2 * i]     = h0;
    ((__half2*)out)[2 * i + 1] = h1;
}

__global__ __launch_bounds__(256) void pack_qkv_h(
    const float* __restrict__ Wq, const float* __restrict__ Wk,
    const float* __restrict__ Wv, __half* __restrict__ Wp)
{
    int i = blockIdx.x * blockDim.x + threadIdx.x;     // float4 index
    int row = (i * 4) >> 10;
    int col = (i * 4) & 1023;
    const float* src;
    if (row < 1024)      src = Wq + (size_t)row * 1024 + col;
    else if (row < 2048) src = Wk + (size_t)(row - 1024) * 1024 + col;
    else                 src = Wv + (size_t)(row - 2048) * 1024 + col;
    float4 v = *(const float4*)src;
    ((__half2*)Wp)[2 * i]     = __floats2half2_rn(v.x, v.y);
    ((__half2*)Wp)[2 * i + 1] = __floats2half2_rn(v.z, v.w);
}

// ---------------------------------------------------------------------------
// Tensor-core flash attention on packed fp16 qkv [8192, 3072].
// Head n=b*16+h: q at col h*64, k at +1024, v at +2048 (row s*4+b).
// fp16->f32 load is exact (fp16 mantissa fits tf32). Output u fp16.
// ---------------------------------------------------------------------------
#define APAD 68
#define ATTN_SMEM_FLOATS (4*64*APAD + 3*64)
#define QKV_SSTRIDE (4*3072)

__global__ __launch_bounds__(256) void attn_tc(
    const __half* __restrict__ qkv, const float* __restrict__ mask,
    __half* __restrict__ u)
{
    extern __shared__ float sm[];
    float* Qs = sm;
    float* Ks = Qs + 64 * APAD;
    float* Vs = Ks + 64 * APAD;
    float* Ps = Vs + 64 * APAD;
    float* rm = Ps + 64 * APAD;
    float* rl = rm + 64;
    float* rc = rl + 64;

    const int n   = blockIdx.y;
    const int bb  = n >> 4;
    const int hh  = n & 15;
    const int s0  = blockIdx.x * 64;
    const int tid = threadIdx.x;
    const int warp = tid >> 5;
    const int lane = tid & 31;
    const int gr   = lane >> 2;
    const int tig  = lane & 3;
    const int wm   = (warp & 3) * 16;
    const int wn   = (warp >> 2) * 32;

    const __half* qb = qkv + (size_t)bb * 3072 + hh * 64;
    const __half* kb = qb + 1024;
    const __half* vb = qb + 2048;

#pragma unroll
    for (int it = 0; it < 4; it++) {
        int lin = tid + it * 256;
        int row = lin >> 4;
        int c4  = (lin & 15) * 4;
        uint2 raw = *(const uint2*)(qb + (size_t)(s0 + row) * QKV_SSTRIDE + c4);
        float2 f0 = __half22float2(((const __half2*)&raw)[0]);
        float2 f1 = __half22float2(((const __half2*)&raw)[1]);
        float4 o; o.x = f0.x; o.y = f0.y; o.z = f1.x; o.w = f1.y;
        *(float4*)(&Qs[row * APAD + c4]) = o;
    }
    if (tid < 64) { rm[tid] = -1e30f; rl[tid] = 0.f; }

    float oacc[4][4];
#pragma unroll
    for (int nt = 0; nt < 4; nt++)
#pragma unroll
        for (int c = 0; c < 4; c++) oacc[nt][c] = 0.f;

    for (int t0 = 0; t0 < SEQ; t0 += 64) {
        __syncthreads();
#pragma unroll
        for (int it = 0; it < 4; it++) {
            int lin = tid + it * 256;
            int row = lin >> 4;
            int c4  = (lin & 15) * 4;
            uint2 rk = *(const uint2*)(kb + (size_t)(t0 + row) * QKV_SSTRIDE + c4);
            float2 k0 = __half22float2(((const __half2*)&rk)[0]);
            float2 k1 = __half22float2(((const __half2*)&rk)[1]);
            float4 ok; ok.x = k0.x; ok.y = k0.y; ok.z = k1.x; ok.w = k1.y;
            *(float4*)(&Ks[row * APAD + c4]) = ok;
            uint2 rv = *(const uint2*)(vb + (size_t)(t0 + row) * QKV_SSTRIDE + c4);
            float2 v0 = __half22float2(((const __half2*)&rv)[0]);
            float2 v1 = __half22float2(((const __half2*)&rv)[1]);
            float4 ov; ov.x = v0.x; ov.y = v0.y; ov.z = v1.x; ov.w = v1.y;
            *(float4*)(&Vs[row * APAD + c4]) = ov;
        }
        __syncthreads();

        float sacc[4][4];
#pragma unroll
        for (int nt = 0; nt < 4; nt++)
#pragma unroll
            for (int c = 0; c < 4; c++) sacc[nt][c] = 0.f;
#pragma unroll
        for (int ks = 0; ks < 64; ks += 8) {
            uint32_t a0 = __float_as_uint(Qs[(wm + gr    ) * APAD + ks + tig    ]);
            uint32_t a1 = __float_as_uint(Qs[(wm + gr + 8) * APAD + ks + tig    ]);
            uint32_t a2 = __float_as_uint(Qs[(wm + gr    ) * APAD + ks + tig + 4]);
            uint32_t a3 = __float_as_uint(Qs[(wm + gr + 8) * APAD + ks + tig + 4]);
#pragma unroll
            for (int nt = 0; nt < 4; nt++) {
                int cc = wn + nt * 8;
                uint32_t b0 = __float_as_uint(Ks[(cc + gr) * APAD + ks + tig    ]);
                uint32_t b1 = __float_as_uint(Ks[(cc + gr) * APAD + ks + tig + 4]);
                mma_tf32(sacc[nt][0], sacc[nt][1], sacc[nt][2], sacc[nt][3],
                         a0, a1, a2, a3, b0, b1);
            }
        }
#pragma unroll
        for (int nt = 0; nt < 4; nt++) {
            int col = wn + nt * 8 + 2 * tig;
#pragma unroll
            for (int h = 0; h < 2; h++) {
                int r = wm + gr + h * 8;
                const float2 mv = *(const float2*)(mask + (size_t)(s0 + r) * SEQ + t0 + col);
                Ps[r * APAD + col    ] = (sacc[nt][h * 2 + 0] + mv.x) * 0.125f;
                Ps[r * APAD + col + 1] = (sacc[nt][h * 2 + 1] + mv.y) * 0.125f;
            }
        }
        __syncthreads();

        {
            int row  = tid >> 2;
            int part = tid & 3;
            float tm = -1e30f;
#pragma unroll
            for (int j = part * 16; j < part * 16 + 16; j++)
                tm = fmaxf(tm, Ps[row * APAD + j]);
            tm = fmaxf(tm, __shfl_xor_sync(0xffffffffu, tm, 1));
            tm = fmaxf(tm, __shfl_xor_sync(0xffffffffu, tm, 2));
            float old_m = rm[row];
            float new_m = fmaxf(old_m, tm);
            float sum = 0.f;
#pragma unroll
            for (int j = part * 16; j < part * 16 + 16; j++) {
                float e = __expf(Ps[row * APAD + j] - new_m);
                Ps[row * APAD + j] = tf32r(e);
                sum += e;
            }
            sum += __shfl_xor_sync(0xffffffffu, sum, 1);
            sum += __shfl_xor_sync(0xffffffffu, sum, 2);
            if (part == 0) {
                float corr = __expf(old_m - new_m);
                rl[row] = rl[row] * corr + sum;
                rm[row] = new_m;
                rc[row] = corr;
            }
        }
        __syncthreads();

        float c_lo = rc[wm + gr];
        float c_hi = rc[wm + gr + 8];
#pragma unroll
        for (int nt = 0; nt < 4; nt++) {
            oacc[nt][0] *= c_lo; oacc[nt][1] *= c_lo;
            oacc[nt][2] *= c_hi; oacc[nt][3] *= c_hi;
        }
#pragma unroll
        for (int ks = 0; ks < 64; ks += 8) {
            uint32_t a0 = __float_as_uint(Ps[(wm + gr    ) * APAD + ks + tig    ]);
            uint32_t a1 = __float_as_uint(Ps[(wm + gr + 8) * APAD + ks + tig    ]);
            uint32_t a2 = __float_as_uint(Ps[(wm + gr    ) * APAD + ks + tig + 4]);
            uint32_t a3 = __float_as_uint(Ps[(wm + gr + 8) * APAD + ks + tig + 4]);
#pragma unroll
            for (int nt = 0; nt < 4; nt++) {
                int cc = wn + nt * 8;
                uint32_t b0 = __float_as_uint(Vs[(ks + tig    ) * APAD + cc + gr]);
                uint32_t b1 = __float_as_uint(Vs[(ks + tig + 4) * APAD + cc + gr]);
                mma_tf32(oacc[nt][0], oacc[nt][1], oacc[nt][2], oacc[nt][3],
                         a0, a1, a2, a3, b0, b1);
            }
        }
    }

    // final normalize + store (fp16)
    {
        float inv_lo = 1.f / rl[wm + gr];
        float inv_hi = 1.f / rl[wm + gr + 8];
#pragma unroll
        for (int nt = 0; nt < 4; nt++) {
            int col = wn + nt * 8 + 2 * tig;
            *(__half2*)(u + (size_t)(s0 + wm + gr) * 4096 + (size_t)n * 64 + col) =
                __floats2half2_rn(oacc[nt][0] * inv_lo, oacc[nt][1] * inv_lo);
            *(__half2*)(u + (size_t)(s0 + wm + gr + 8) * 4096 + (size_t)n * 64 + col) =
                __floats2half2_rn(oacc[nt][2] * inv_hi, oacc[nt][3] * inv_hi);
        }
    }
}

// ---------------------------------------------------------------------------
// LayerNorm over last dim (1024); optional fp16 secondary output.
// ---------------------------------------------------------------------------
__global__ __launch_bounds__(256) void ln_kernel(
    const float* __restrict__ in, const float* __restrict__ g,
    const float* __restrict__ be, float* __restrict__ out,
    __half* __restrict__ outh)
{
    const int row = blockIdx.x;
    const int tid = threadIdx.x;
    __shared__ float red[8];
    __shared__ float s_mu, s_rstd;

    float4 v = *(const float4*)(in + (size_t)row * DMODEL + tid * 4);
    float s = v.x + v.y + v.z + v.w;
#pragma unroll
    for (int o = 16; o > 0; o >>= 1) s += __shfl_xor_sync(0xffffffffu, s, o);
    if ((tid & 31) == 0) red[tid >> 5] = s;
    __syncthreads();
    if (tid < 8) {
        float t = red[tid];
#pragma unroll
        for (int o = 4; o > 0; o >>= 1) t += __shfl_xor_sync(0xffu, t, o);
        if (tid == 0) s_mu = t * (1.f / DMODEL);
    }
    __syncthreads();
    float mu = s_mu;
    float d0 = v.x - mu, d1 = v.y - mu, d2 = v.z - mu, d3 = v.w - mu;
    float s2 = d0 * d0 + d1 * d1 + d2 * d2 + d3 * d3;
#pragma unroll
    for (int o = 16; o > 0; o >>= 1) s2 += __shfl_xor_sync(0xffffffffu, s2, o);
    if ((tid & 31) == 0) red[tid >> 5] = s2;
    __syncthreads();
    if (tid < 8) {
        float t = red[tid];
#pragma unroll
        for (int o = 4; o > 0; o >>= 1) t += __shfl_xor_sync(0xffu, t, o);
        if (tid == 0) s_rstd = rsqrtf(t * (1.f / DMODEL) + LN_EPS);
    }
    __syncthreads();
    float rstd = s_rstd;
    float4 gv = *(const float4*)(g + tid * 4);
    float4 bv = *(const float4*)(be + tid * 4);
    float4 ov;
    ov.x = d0 * rstd * gv.x + bv.x;
    ov.y = d1 * rstd * gv.y + bv.y;
    ov.z = d2 * rstd * gv.z + bv.z;
    ov.w = d3 * rstd * gv.w + bv.w;
    *(float4*)(out + (size_t)row * DMODEL + tid * 4) = ov;
    if (outh != nullptr) {
        __half2 h0 = __floats2half2_rn(ov.x, ov.y);
        __half2 h1 = __floats2half2_rn(ov.z, ov.w);
        *(__half2*)(outh + (size_t)row * DMODEL + tid * 4)     = h0;
        *(__half2*)(outh + (size_t)row * DMODEL + tid * 4 + 2) = h1;
    }
}

// ---------------------------------------------------------------------------
extern "C" void kernel_launch(void* const* d_in, const int* in_sizes, int n_in,
                              void* d_out, int out_size)
{
    const float* x    = (const float*)d_in[0];
    const float* mask = (const float*)d_in[1];
    const float* Wq   = (const float*)d_in[2];
    const float* Wk   = (const float*)d_in[3];
    const float* Wv   = (const float*)d_in[4];
    const float* Wc   = (const float*)d_in[5];
    const float* W1   = (const float*)d_in[6];
    const float* b1   = (const float*)d_in[7];
    const float* W2   = (const float*)d_in[8];
    const float* b2   = (const float*)d_in[9];
    const float* g1   = (const float*)d_in[10];
    const float* be1  = (const float*)d_in[11];
    const float* g2   = (const float*)d_in[12];
    const float* be2  = (const float*)d_in[13];
    float* out = (float*)d_out;

    __half *xh, *wph, *wch, *w1h, *w2h, *qkvh, *uh, *t2h, *hidh;
    float *t1, *t2, *t3;
    cudaGetSymbolAddress((void**)&xh,   g_xh);
    cudaGetSymbolAddress((void**)&wph,  g_wph);
    cudaGetSymbolAddress((void**)&wch,  g_wch);
    cudaGetSymbolAddress((void**)&w1h,  g_w1h);
    cudaGetSymbolAddress((void**)&w2h,  g_w2h);
    cudaGetSymbolAddress((void**)&qkvh, g_qkvh);
    cudaGetSymbolAddress((void**)&uh,   g_uh);
    cudaGetSymbolAddress((void**)&t2h,  g_t2h);
    cudaGetSymbolAddress((void**)&hidh, g_hidh);
    cudaGetSymbolAddress((void**)&t1,   g_t1);
    cudaGetSymbolAddress((void**)&t2,   g_t2);
    cudaGetSymbolAddress((void**)&t3,   g_t3);

    const int attn_smem = ATTN_SMEM_FLOATS * sizeof(float);
    cudaFuncSetAttribute(attn_tc, cudaFuncAttributeMaxDynamicSharedMemorySize, attn_smem);
    cudaFuncSetAttribute(gemm_h, cudaFuncAttributeMaxDynamicSharedMemorySize, GEMM_SMEM_BYTES);

    dim3 blk(256);

    // fp16 conversions
    cvt_h<<<(MROWS * DMODEL / 4) / 256, blk>>>(x, xh);
    pack_qkv_h<<<(3072 * DMODEL / 4) / 256, blk>>>(Wq, Wk, Wv, wph);
    cvt_h<<<(DMODEL * DMODEL / 4) / 256, blk>>>(Wc, wch);
    cvt_h<<<(FFDIM * DMODEL / 4) / 256, blk>>>(W1, w1h);
    cvt_h<<<(DMODEL * FFDIM / 4) / 256, blk>>>(W2, w2h);

    // fused QKV projection -> qkvh fp16 [8192, 3072]
    gemm_h<<<dim3(3072 / 128, MROWS / 128), blk, GEMM_SMEM_BYTES>>>(
        xh, wph, nullptr, nullptr, qkvh, 3072, DMODEL, 0);

    // attention -> uh fp16
    attn_tc<<<dim3(SEQ / 64, 64), blk, attn_smem>>>(qkvh, mask, uh);

    // x + u @ Wc^T -> t1 f32;  LN1 -> t2 f32 + t2h fp16
    gemm_h<<<dim3(DMODEL / 128, MROWS / 128), blk, GEMM_SMEM_BYTES>>>(
        uh, wch, nullptr, x, t1, DMODEL, DMODEL, 3);
    ln_kernel<<<MROWS, blk>>>(t1, g1, be1, t2, t2h);

    // FFN: relu(t2@W1^T+b1) -> hidh fp16;  hid@W2^T+b2 + t2 -> t3;  LN2 -> out
    gemm_h<<<dim3(FFDIM / 128, MROWS / 128), blk, GEMM_SMEM_BYTES>>>(
        t2h, w1h, b1, nullptr, hidh, FFDIM, DMODEL, 1);
    gemm_h<<<dim3(DMODEL / 128, MROWS / 128), blk, GEMM_SMEM_BYTES>>>(
        hidh, w2h, b2, t2, t3, DMODEL, FFDIM, 2);
    ln_kernel<<<MROWS, blk>>>(t3, g2, be2, out, nullptr);
}

// round 9
// speedup vs baseline: 5.7546x; 1.2311x over previous
#include <cuda_runtime.h>
#include <cuda_fp16.h>
#include <math.h>
#include <stdint.h>

// ---------------------------------------------------------------------------
// PTransformerBlock: S=2048 B=4 D=1024 H=16 K=64 FF=4096.
// Round 9: attention matmuls on fp16 m16n8k16 (ldmatrix + ldmatrix.trans),
//          fp16 GEMMs (R8), fp16 inter-kernel tensors.
// ---------------------------------------------------------------------------

#define SEQ   2048
#define BATCH 4
#define DMODEL 1024
#define FFDIM 4096
#define MROWS (SEQ*BATCH)   // 8192
#define LN_EPS 1e-5f

// scratch (allocation-free: device globals)
__device__ __half g_xh  [MROWS * DMODEL];
__device__ __half g_wph [3072 * DMODEL];
__device__ __half g_wch [DMODEL * DMODEL];
__device__ __half g_w1h [FFDIM * DMODEL];
__device__ __half g_w2h [DMODEL * FFDIM];
__device__ __half g_qkvh[MROWS * 3072];
__device__ __half g_uh  [MROWS * DMODEL];
__device__ __half g_t2h [MROWS * DMODEL];
__device__ __half g_hidh[MROWS * FFDIM];
__device__ float  g_t1  [MROWS * DMODEL];
__device__ float  g_t2  [MROWS * DMODEL];
__device__ float  g_t3  [MROWS * DMODEL];

__device__ __forceinline__ void mma_f16(
    float& d0, float& d1, float& d2, float& d3,
    uint32_t a0, uint32_t a1, uint32_t a2, uint32_t a3,
    uint32_t b0, uint32_t b1)
{
    asm volatile(
        "mma.sync.aligned.m16n8k16.row.col.f32.f16.f16.f32 "
        "{%0,%1,%2,%3}, {%4,%5,%6,%7}, {%8,%9}, {%0,%1,%2,%3};"
        : "+f"(d0), "+f"(d1), "+f"(d2), "+f"(d3)
        : "r"(a0), "r"(a1), "r"(a2), "r"(a3), "r"(b0), "r"(b1));
}

__device__ __forceinline__ void ldsm4(
    uint32_t& r0, uint32_t& r1, uint32_t& r2, uint32_t& r3, uint32_t addr)
{
    asm volatile("ldmatrix.sync.aligned.m8n8.x4.shared.b16 {%0,%1,%2,%3}, [%4];"
                 : "=r"(r0), "=r"(r1), "=r"(r2), "=r"(r3) : "r"(addr));
}
__device__ __forceinline__ void ldsm4_t(
    uint32_t& r0, uint32_t& r1, uint32_t& r2, uint32_t& r3, uint32_t addr)
{
    asm volatile("ldmatrix.sync.aligned.m8n8.x4.trans.shared.b16 {%0,%1,%2,%3}, [%4];"
                 : "=r"(r0), "=r"(r1), "=r"(r2), "=r"(r3) : "r"(addr));
}

__device__ __forceinline__ void cp16(uint32_t s, const void* g) {
    asm volatile("cp.async.cg.shared.global [%0], [%1], 16;" :: "r"(s), "l"(g));
}
__device__ __forceinline__ uint32_t saddr(const void* p) {
    return (uint32_t)__cvta_generic_to_shared(p);
}
#define SWZ128(o) ((o) ^ (((o) >> 3) & 0x70))

// ---------------------------------------------------------------------------
// fp16 tensor-core GEMM (unchanged from R8).
// EPI: 0=none,fp16  1=+bias,relu,fp16  2=+bias,+res,f32  3=+res,f32
// ---------------------------------------------------------------------------
#define STAGE_BYTES 32768
#define NSTAGE 3
#define GEMM_SMEM_BYTES (NSTAGE * STAGE_BYTES)

__device__ __forceinline__ void load_tile_h(
    uint32_t base, const __half* __restrict__ A, const __half* __restrict__ W,
    int m0, int n0, int Kd, int k0, int tid)
{
#pragma unroll
    for (int it = 0; it < 4; it++) {
        int lin = tid + it * 256;
        int row = lin >> 3;
        int ch  = lin & 7;
        uint32_t off = (uint32_t)(row * 128 + ch * 16);
        uint32_t sw  = SWZ128(off);
        cp16(base + sw,         A + (size_t)(m0 + row) * Kd + k0 + ch * 8);
        cp16(base + 16384 + sw, W + (size_t)(n0 + row) * Kd + k0 + ch * 8);
    }
}

__global__ __launch_bounds__(256, 2) void gemm_h(
    const __half* __restrict__ A, const __half* __restrict__ W,
    const float* __restrict__ bias, const float* __restrict__ res,
    void* __restrict__ Cv, int N, int Kd, int EPI)
{
    extern __shared__ __align__(1024) char smem[];

    const int tid  = threadIdx.x;
    const int warp = tid >> 5;
    const int lane = tid & 31;
    const int gr   = lane >> 2;
    const int tig  = lane & 3;
    const int wm   = (warp & 1) * 64;
    const int wn   = (warp >> 1) * 32;
    const int m0   = blockIdx.y * 128;
    const int n0   = blockIdx.x * 128;

    const uint32_t sb = saddr(smem);

    float acc[4][4][4];
#pragma unroll
    for (int mt = 0; mt < 4; mt++)
#pragma unroll
        for (int nt = 0; nt < 4; nt++)
#pragma unroll
            for (int c = 0; c < 4; c++) acc[mt][nt][c] = 0.f;

    const int ktiles = Kd >> 6;

#pragma unroll
    for (int pf = 0; pf < NSTAGE; pf++) {
        load_tile_h(sb + pf * STAGE_BYTES, A, W, m0, n0, Kd, pf * 64, tid);
        asm volatile("cp.async.commit_group;");
    }

    for (int t = 0; t < ktiles; t++) {
        {
            int rem = ktiles - 1 - t;
            if (rem >= 2)      asm volatile("cp.async.wait_group 2;");
            else if (rem == 1) asm volatile("cp.async.wait_group 1;");
            else               asm volatile("cp.async.wait_group 0;");
        }
        __syncthreads();

        const uint32_t sA = sb + (uint32_t)((t % NSTAGE) * STAGE_BYTES);
        const uint32_t sB = sA + 16384u;

#pragma unroll
        for (int ks = 0; ks < 4; ks++) {
            uint32_t a[4][4], b[4][2];
#pragma unroll
            for (int mt = 0; mt < 4; mt++) {
                uint32_t off = (uint32_t)((wm + mt * 16 + (lane & 15)) * 128
                                          + ks * 32 + ((lane >> 4) << 4));
                ldsm4(a[mt][0], a[mt][1], a[mt][2], a[mt][3], sA + SWZ128(off));
            }
#pragma unroll
            for (int np = 0; np < 2; np++) {
                uint32_t off = (uint32_t)((wn + np * 16 + (lane & 7)
                                           + ((lane >> 4) & 1) * 8) * 128
                                          + ks * 32 + (((lane >> 3) & 1) << 4));
                ldsm4(b[2 * np][0], b[2 * np][1], b[2 * np + 1][0], b[2 * np + 1][1],
                      sB + SWZ128(off));
            }
#pragma unroll
            for (int mt = 0; mt < 4; mt++)
#pragma unroll
                for (int nt = 0; nt < 4; nt++)
                    mma_f16(acc[mt][nt][0], acc[mt][nt][1], acc[mt][nt][2], acc[mt][nt][3],
                            a[mt][0], a[mt][1], a[mt][2], a[mt][3],
                            b[nt][0], b[nt][1]);
        }
        __syncthreads();

        if (t + NSTAGE < ktiles) {
            load_tile_h(sA, A, W, m0, n0, Kd, (t + NSTAGE) * 64, tid);
            asm volatile("cp.async.commit_group;");
        }
    }

#pragma unroll
    for (int mt = 0; mt < 4; mt++) {
#pragma unroll
        for (int nt = 0; nt < 4; nt++) {
            int row = m0 + wm + mt * 16 + gr;
            int col = n0 + wn + nt * 8 + 2 * tig;
#pragma unroll
            for (int h = 0; h < 2; h++) {
                int r = row + h * 8;
                float c0 = acc[mt][nt][h * 2 + 0];
                float c1 = acc[mt][nt][h * 2 + 1];
                if (EPI == 0) {
                    *(__half2*)((__half*)Cv + (size_t)r * N + col) =
                        __floats2half2_rn(c0, c1);
                } else if (EPI == 1) {
                    c0 = fmaxf(c0 + bias[col], 0.f);
                    c1 = fmaxf(c1 + bias[col + 1], 0.f);
                    *(__half2*)((__half*)Cv + (size_t)r * N + col) =
                        __floats2half2_rn(c0, c1);
                } else if (EPI == 2) {
                    const float2 rv = *(const float2*)(res + (size_t)r * N + col);
                    float2 o; o.x = c0 + bias[col] + rv.x; o.y = c1 + bias[col + 1] + rv.y;
                    *(float2*)((float*)Cv + (size_t)r * N + col) = o;
                } else {
                    const float2 rv = *(const float2*)(res + (size_t)r * N + col);
                    float2 o; o.x = c0 + rv.x; o.y = c1 + rv.y;
                    *(float2*)((float*)Cv + (size_t)r * N + col) = o;
                }
            }
        }
    }
}

// ---------------------------------------------------------------------------
// f32 -> fp16 converters
// ---------------------------------------------------------------------------
__global__ __launch_bounds__(256) void cvt_h(
    const float* __restrict__ in, __half* __restrict__ out)
{
    int i = blockIdx.x * blockDim.x + threadIdx.x;
    float4 v = ((const float4*)in)[i];
    ((__half2*)out)[2 * i]     = __floats2half2_rn(v.x, v.y);
    ((__half2*)out)[2 * i + 1] = __floats2half2_rn(v.z, v.w);
}

__global__ __launch_bounds__(256) void pack_qkv_h(
    const float* __restrict__ Wq, const float* __restrict__ Wk,
    const float* __restrict__ Wv, __half* __restrict__ Wp)
{
    int i = blockIdx.x * blockDim.x + threadIdx.x;
    int row = (i * 4) >> 10;
    int col = (i * 4) & 1023;
    const float* src;
    if (row < 1024)      src = Wq + (size_t)row * 1024 + col;
    else if (row < 2048) src = Wk + (size_t)(row - 1024) * 1024 + col;
    else                 src = Wv + (size_t)(row - 2048) * 1024 + col;
    float4 v = *(const float4*)src;
    ((__half2*)Wp)[2 * i]     = __floats2half2_rn(v.x, v.y);
    ((__half2*)Wp)[2 * i + 1] = __floats2half2_rn(v.z, v.w);
}

// ---------------------------------------------------------------------------
// fp16 tensor-core flash attention on packed qkv [8192, 3072].
// One block = 64 q-rows of one head; 8 warps, warp tile 16(m) x 32(n).
// QK^T: both non-trans ldmatrix (k-contiguous). PV: P [s][t] non-trans A,
// V [t][c] via ldmatrix.trans -> V^T B-fragment. fp16 rows padded to 144B.
// ---------------------------------------------------------------------------
#define HSTR 72                      // halves per padded row (144 B)
#define OFF_Q 0
#define OFF_K (64*HSTR*2)            // 9216
#define OFF_V (2*64*HSTR*2)
#define OFF_P (3*64*HSTR*2)
#define OFF_S (4*64*HSTR*2)          // f32 scores [64][68]
#define SPAD 68
#define OFF_RM (OFF_S + 64*SPAD*4)
#define OFF_RL (OFF_RM + 256)
#define OFF_RC (OFF_RL + 256)
#define ATTN_SMEM_BYTES (OFF_RC + 256)
#define QKV_SSTRIDE (4*3072)

__global__ __launch_bounds__(256) void attn_h(
    const __half* __restrict__ qkv, const float* __restrict__ mask,
    __half* __restrict__ u)
{
    extern __shared__ __align__(1024) char smc[];
    __half* Qh = (__half*)(smc + OFF_Q);
    __half* Kh = (__half*)(smc + OFF_K);
    __half* Vh = (__half*)(smc + OFF_V);
    __half* Ph = (__half*)(smc + OFF_P);
    float*  Sf = (float*)(smc + OFF_S);
    float*  rm = (float*)(smc + OFF_RM);
    float*  rl = (float*)(smc + OFF_RL);
    float*  rc = (float*)(smc + OFF_RC);

    const int n   = blockIdx.y;          // head (b*16+h)
    const int bb  = n >> 4;
    const int hh  = n & 15;
    const int s0  = blockIdx.x * 64;
    const int tid = threadIdx.x;
    const int warp = tid >> 5;
    const int lane = tid & 31;
    const int gr   = lane >> 2;
    const int tig  = lane & 3;
    const int wm   = (warp & 3) * 16;
    const int wn   = (warp >> 2) * 32;

    const uint32_t sQ = saddr(Qh);
    const uint32_t sK = saddr(Kh);
    const uint32_t sV = saddr(Vh);
    const uint32_t sP = saddr(Ph);

    const __half* qb = qkv + (size_t)bb * 3072 + hh * 64;
    const __half* kb = qb + 1024;
    const __half* vb = qb + 2048;

    // load Q tile fp16 (64 rows x 64 halves; 8 halves per thread x2)
#pragma unroll
    for (int it = 0; it < 2; it++) {
        int lin = tid + it * 256;        // 0..511
        int row = lin >> 3;
        int ch  = (lin & 7) * 8;
        uint4 v = *(const uint4*)(qb + (size_t)(s0 + row) * QKV_SSTRIDE + ch);
        *(uint4*)(Qh + row * HSTR + ch) = v;
    }
    if (tid < 64) { rm[tid] = -1e30f; rl[tid] = 0.f; }

    float oacc[4][4];
#pragma unroll
    for (int nt = 0; nt < 4; nt++)
#pragma unroll
        for (int c = 0; c < 4; c++) oacc[nt][c] = 0.f;

    for (int t0 = 0; t0 < SEQ; t0 += 64) {
        __syncthreads();
#pragma unroll
        for (int it = 0; it < 2; it++) {
            int lin = tid + it * 256;
            int row = lin >> 3;
            int ch  = (lin & 7) * 8;
            uint4 vk = *(const uint4*)(kb + (size_t)(t0 + row) * QKV_SSTRIDE + ch);
            *(uint4*)(Kh + row * HSTR + ch) = vk;
            uint4 vv = *(const uint4*)(vb + (size_t)(t0 + row) * QKV_SSTRIDE + ch);
            *(uint4*)(Vh + row * HSTR + ch) = vv;
        }
        __syncthreads();

        // ---- S = Q K^T (fp16 m16n8k16) ----
        float sacc[4][4];
#pragma unroll
        for (int nt = 0; nt < 4; nt++)
#pragma unroll
            for (int c = 0; c < 4; c++) sacc[nt][c] = 0.f;
#pragma unroll
        for (int ks = 0; ks < 4; ks++) {
            uint32_t a0, a1, a2, a3;
            {
                uint32_t off = (uint32_t)((wm + (lane & 15)) * 144
                                          + ks * 32 + ((lane >> 4) << 4));
                ldsm4(a0, a1, a2, a3, sQ + off);
            }
#pragma unroll
            for (int np = 0; np < 2; np++) {
                uint32_t b0, b1, b2, b3;
                uint32_t off = (uint32_t)((wn + np * 16 + (lane & 7)
                                           + ((lane >> 4) & 1) * 8) * 144
                                          + ks * 32 + (((lane >> 3) & 1) << 4));
                ldsm4(b0, b1, b2, b3, sK + off);
                mma_f16(sacc[2*np][0], sacc[2*np][1], sacc[2*np][2], sacc[2*np][3],
                        a0, a1, a2, a3, b0, b1);
                mma_f16(sacc[2*np+1][0], sacc[2*np+1][1], sacc[2*np+1][2], sacc[2*np+1][3],
                        a0, a1, a2, a3, b2, b3);
            }
        }
        // (S + mask) * 1/sqrt(K) -> Sf   [mask BEFORE scaling, faithful]
#pragma unroll
        for (int nt = 0; nt < 4; nt++) {
            int col = wn + nt * 8 + 2 * tig;
#pragma unroll
            for (int h = 0; h < 2; h++) {
                int r = wm + gr + h * 8;
                const float2 mv = *(const float2*)(mask + (size_t)(s0 + r) * SEQ + t0 + col);
                Sf[r * SPAD + col    ] = (sacc[nt][h * 2 + 0] + mv.x) * 0.125f;
                Sf[r * SPAD + col + 1] = (sacc[nt][h * 2 + 1] + mv.y) * 0.125f;
            }
        }
        __syncthreads();

        // ---- online softmax (4 threads per row), write P fp16 ----
        {
            int row  = tid >> 2;
            int part = tid & 3;
            float tm = -1e30f;
#pragma unroll
            for (int j = part * 16; j < part * 16 + 16; j++)
                tm = fmaxf(tm, Sf[row * SPAD + j]);
            tm = fmaxf(tm, __shfl_xor_sync(0xffffffffu, tm, 1));
            tm = fmaxf(tm, __shfl_xor_sync(0xffffffffu, tm, 2));
            float old_m = rm[row];
            float new_m = fmaxf(old_m, tm);
            float sum = 0.f;
#pragma unroll
            for (int j = part * 16; j < part * 16 + 16; j += 2) {
                float e0 = __expf(Sf[row * SPAD + j    ] - new_m);
                float e1 = __expf(Sf[row * SPAD + j + 1] - new_m);
                *(__half2*)(Ph + row * HSTR + j) = __floats2half2_rn(e0, e1);
                sum += e0 + e1;
            }
            sum += __shfl_xor_sync(0xffffffffu, sum, 1);
            sum += __shfl_xor_sync(0xffffffffu, sum, 2);
            if (part == 0) {
                float corr = __expf(old_m - new_m);
                rl[row] = rl[row] * corr + sum;
                rm[row] = new_m;
                rc[row] = corr;
            }
        }
        __syncthreads();

        // ---- O = O*corr + P @ V (fp16; V via ldmatrix.trans) ----
        float c_lo = rc[wm + gr];
        float c_hi = rc[wm + gr + 8];
#pragma unroll
        for (int nt = 0; nt < 4; nt++) {
            oacc[nt][0] *= c_lo; oacc[nt][1] *= c_lo;
            oacc[nt][2] *= c_hi; oacc[nt][3] *= c_hi;
        }
#pragma unroll
        for (int ks = 0; ks < 4; ks++) {
            uint32_t a0, a1, a2, a3;
            {
                uint32_t off = (uint32_t)((wm + (lane & 15)) * 144
                                          + ks * 32 + ((lane >> 4) << 4));
                ldsm4(a0, a1, a2, a3, sP + off);
            }
#pragma unroll
            for (int np = 0; np < 2; np++) {
                uint32_t b0, b1, b2, b3;
                int vrow = ks * 16 + (lane & 7) + ((lane >> 3) & 1) * 8;
                int vcol = wn + np * 16 + ((lane >> 4) & 1) * 8;
                uint32_t off = (uint32_t)(vrow * 144 + vcol * 2);
                ldsm4_t(b0, b1, b2, b3, sV + off);
                mma_f16(oacc[2*np][0], oacc[2*np][1], oacc[2*np][2], oacc[2*np][3],
                        a0, a1, a2, a3, b0, b1);
                mma_f16(oacc[2*np+1][0], oacc[2*np+1][1], oacc[2*np+1][2], oacc[2*np+1][3],
                        a0, a1, a2, a3, b2, b3);
            }
        }
    }

    // final normalize + store fp16
    {
        float inv_lo = 1.f / rl[wm + gr];
        float inv_hi = 1.f / rl[wm + gr + 8];
#pragma unroll
        for (int nt = 0; nt < 4; nt++) {
            int col = wn + nt * 8 + 2 * tig;
            *(__half2*)(u + (size_t)(s0 + wm + gr) * 4096 + (size_t)n * 64 + col) =
                __floats2half2_rn(oacc[nt][0] * inv_lo, oacc[nt][1] * inv_lo);
            *(__half2*)(u + (size_t)(s0 + wm + gr + 8) * 4096 + (size_t)n * 64 + col) =
                __floats2half2_rn(oacc[nt][2] * inv_hi, oacc[nt][3] * inv_hi);
        }
    }
}

// ---------------------------------------------------------------------------
// LayerNorm over last dim (1024); optional fp16 secondary output.
// ---------------------------------------------------------------------------
__global__ __launch_bounds__(256) void ln_kernel(
    const float* __restrict__ in, const float* __restrict__ g,
    const float* __restrict__ be, float* __restrict__ out,
    __half* __restrict__ outh)
{
    const int row = blockIdx.x;
    const int tid = threadIdx.x;
    __shared__ float red[8];
    __shared__ float s_mu, s_rstd;

    float4 v = *(const float4*)(in + (size_t)row * DMODEL + tid * 4);
    float s = v.x + v.y + v.z + v.w;
#pragma unroll
    for (int o = 16; o > 0; o >>= 1) s += __shfl_xor_sync(0xffffffffu, s, o);
    if ((tid & 31) == 0) red[tid >> 5] = s;
    __syncthreads();
    if (tid < 8) {
        float t = red[tid];
#pragma unroll
        for (int o = 4; o > 0; o >>= 1) t += __shfl_xor_sync(0xffu, t, o);
        if (tid == 0) s_mu = t * (1.f / DMODEL);
    }
    __syncthreads();
    float mu = s_mu;
    float d0 = v.x - mu, d1 = v.y - mu, d2 = v.z - mu, d3 = v.w - mu;
    float s2 = d0 * d0 + d1 * d1 + d2 * d2 + d3 * d3;
#pragma unroll
    for (int o = 16; o > 0; o >>= 1) s2 += __shfl_xor_sync(0xffffffffu, s2, o);
    if ((tid & 31) == 0) red[tid >> 5] = s2;
    __syncthreads();
    if (tid < 8) {
        float t = red[tid];
#pragma unroll
        for (int o = 4; o > 0; o >>= 1) t += __shfl_xor_sync(0xffu, t, o);
        if (tid == 0) s_rstd = rsqrtf(t * (1.f / DMODEL) + LN_EPS);
    }
    __syncthreads();
    float rstd = s_rstd;
    float4 gv = *(const float4*)(g + tid * 4);
    float4 bv = *(const float4*)(be + tid * 4);
    float4 ov;
    ov.x = d0 * rstd * gv.x + bv.x;
    ov.y = d1 * rstd * gv.y + bv.y;
    ov.z = d2 * rstd * gv.z + bv.z;
    ov.w = d3 * rstd * gv.w + bv.w;
    *(float4*)(out + (size_t)row * DMODEL + tid * 4) = ov;
    if (outh != nullptr) {
        *(__half2*)(outh + (size_t)row * DMODEL + tid * 4)     = __floats2half2_rn(ov.x, ov.y);
        *(__half2*)(outh + (size_t)row * DMODEL + tid * 4 + 2) = __floats2half2_rn(ov.z, ov.w);
    }
}

// ---------------------------------------------------------------------------
extern "C" void kernel_launch(void* const* d_in, const int* in_sizes, int n_in,
                              void* d_out, int out_size)
{
    const float* x    = (const float*)d_in[0];
    const float* mask = (const float*)d_in[1];
    const float* Wq   = (const float*)d_in[2];
    const float* Wk   = (const float*)d_in[3];
    const float* Wv   = (const float*)d_in[4];
    const float* Wc   = (const float*)d_in[5];
    const float* W1   = (const float*)d_in[6];
    const float* b1   = (const float*)d_in[7];
    const float* W2   = (const float*)d_in[8];
    const float* b2   = (const float*)d_in[9];
    const float* g1   = (const float*)d_in[10];
    const float* be1  = (const float*)d_in[11];
    const float* g2   = (const float*)d_in[12];
    const float* be2  = (const float*)d_in[13];
    float* out = (float*)d_out;

    __half *xh, *wph, *wch, *w1h, *w2h, *qkvh, *uh, *t2h, *hidh;
    float *t1, *t2, *t3;
    cudaGetSymbolAddress((void**)&xh,   g_xh);
    cudaGetSymbolAddress((void**)&wph,  g_wph);
    cudaGetSymbolAddress((void**)&wch,  g_wch);
    cudaGetSymbolAddress((void**)&w1h,  g_w1h);
    cudaGetSymbolAddress((void**)&w2h,  g_w2h);
    cudaGetSymbolAddress((void**)&qkvh, g_qkvh);
    cudaGetSymbolAddress((void**)&uh,   g_uh);
    cudaGetSymbolAddress((void**)&t2h,  g_t2h);
    cudaGetSymbolAddress((void**)&hidh, g_hidh);
    cudaGetSymbolAddress((void**)&t1,   g_t1);
    cudaGetSymbolAddress((void**)&t2,   g_t2);
    cudaGetSymbolAddress((void**)&t3,   g_t3);

    cudaFuncSetAttribute(attn_h, cudaFuncAttributeMaxDynamicSharedMemorySize, ATTN_SMEM_BYTES);
    cudaFuncSetAttribute(gemm_h, cudaFuncAttributeMaxDynamicSharedMemorySize, GEMM_SMEM_BYTES);

    dim3 blk(256);

    // fp16 conversions
    cvt_h<<<(MROWS * DMODEL / 4) / 256, blk>>>(x, xh);
    pack_qkv_h<<<(3072 * DMODEL / 4) / 256, blk>>>(Wq, Wk, Wv, wph);
    cvt_h<<<(DMODEL * DMODEL / 4) / 256, blk>>>(Wc, wch);
    cvt_h<<<(FFDIM * DMODEL / 4) / 256, blk>>>(W1, w1h);
    cvt_h<<<(DMODEL * FFDIM / 4) / 256, blk>>>(W2, w2h);

    // fused QKV projection -> qkvh fp16 [8192, 3072]
    gemm_h<<<dim3(3072 / 128, MROWS / 128), blk, GEMM_SMEM_BYTES>>>(
        xh, wph, nullptr, nullptr, qkvh, 3072, DMODEL, 0);

    // attention -> uh fp16
    attn_h<<<dim3(SEQ / 64, 64), blk, ATTN_SMEM_BYTES>>>(qkvh, mask, uh);

    // x + u @ Wc^T -> t1 f32;  LN1 -> t2 f32 + t2h fp16
    gemm_h<<<dim3(DMODEL / 128, MROWS / 128), blk, GEMM_SMEM_BYTES>>>(
        uh, wch, nullptr, x, t1, DMODEL, DMODEL, 3);
    ln_kernel<<<MROWS, blk>>>(t1, g1, be1, t2, t2h);

    // FFN: relu(t2@W1^T+b1) -> hidh;  hid@W2^T+b2 + t2 -> t3;  LN2 -> out
    gemm_h<<<dim3(FFDIM / 128, MROWS / 128), blk, GEMM_SMEM_BYTES>>>(
        t2h, w1h, b1, nullptr, hidh, FFDIM, DMODEL, 1);
    gemm_h<<<dim3(DMODEL / 128, MROWS / 128), blk, GEMM_SMEM_BYTES>>>(
        hidh, w2h, b2, t2, t3, DMODEL, FFDIM, 2);
    ln_kernel<<<MROWS, blk>>>(t3, g2, be2, out, nullptr);
}

// round 11
// speedup vs baseline: 7.5158x; 1.3061x over previous
#include <cuda_runtime.h>
#include <cuda_fp16.h>
#include <math.h>
#include <stdint.h>

// ---------------------------------------------------------------------------
// PTransformerBlock: S=2048 B=4 D=1024 H=16 K=64 FF=4096.
// Round 11 (= R10 with compile fix): FA2-style register-resident attention,
//           fp16 GEMMs, fp16 inter-kernel tensors.
// ---------------------------------------------------------------------------

#define SEQ   2048
#define BATCH 4
#define DMODEL 1024
#define FFDIM 4096
#define MROWS (SEQ*BATCH)   // 8192
#define LN_EPS 1e-5f

// scratch (allocation-free: device globals)
__device__ __half g_xh  [MROWS * DMODEL];
__device__ __half g_wph [3072 * DMODEL];
__device__ __half g_wch [DMODEL * DMODEL];
__device__ __half g_w1h [FFDIM * DMODEL];
__device__ __half g_w2h [DMODEL * FFDIM];
__device__ __half g_qkvh[MROWS * 3072];
__device__ __half g_uh  [MROWS * DMODEL];
__device__ __half g_t2h [MROWS * DMODEL];
__device__ __half g_hidh[MROWS * FFDIM];
__device__ float  g_t1  [MROWS * DMODEL];
__device__ float  g_t2  [MROWS * DMODEL];
__device__ float  g_t3  [MROWS * DMODEL];

__device__ __forceinline__ uint32_t h2u(__half2 h) {
    union { __half2 h; uint32_t u; } c;
    c.h = h;
    return c.u;
}

__device__ __forceinline__ void mma_f16(
    float& d0, float& d1, float& d2, float& d3,
    uint32_t a0, uint32_t a1, uint32_t a2, uint32_t a3,
    uint32_t b0, uint32_t b1)
{
    asm volatile(
        "mma.sync.aligned.m16n8k16.row.col.f32.f16.f16.f32 "
        "{%0,%1,%2,%3}, {%4,%5,%6,%7}, {%8,%9}, {%0,%1,%2,%3};"
        : "+f"(d0), "+f"(d1), "+f"(d2), "+f"(d3)
        : "r"(a0), "r"(a1), "r"(a2), "r"(a3), "r"(b0), "r"(b1));
}

__device__ __forceinline__ void ldsm4(
    uint32_t& r0, uint32_t& r1, uint32_t& r2, uint32_t& r3, uint32_t addr)
{
    asm volatile("ldmatrix.sync.aligned.m8n8.x4.shared.b16 {%0,%1,%2,%3}, [%4];"
                 : "=r"(r0), "=r"(r1), "=r"(r2), "=r"(r3) : "r"(addr));
}
__device__ __forceinline__ void ldsm4_t(
    uint32_t& r0, uint32_t& r1, uint32_t& r2, uint32_t& r3, uint32_t addr)
{
    asm volatile("ldmatrix.sync.aligned.m8n8.x4.trans.shared.b16 {%0,%1,%2,%3}, [%4];"
                 : "=r"(r0), "=r"(r1), "=r"(r2), "=r"(r3) : "r"(addr));
}

__device__ __forceinline__ void cp16(uint32_t s, const void* g) {
    asm volatile("cp.async.cg.shared.global [%0], [%1], 16;" :: "r"(s), "l"(g));
}
__device__ __forceinline__ uint32_t saddr(const void* p) {
    return (uint32_t)__cvta_generic_to_shared(p);
}
#define SWZ128(o) ((o) ^ (((o) >> 3) & 0x70))

// ---------------------------------------------------------------------------
// fp16 tensor-core GEMM (unchanged from R8/R9).
// EPI: 0=none,fp16  1=+bias,relu,fp16  2=+bias,+res,f32  3=+res,f32
// ---------------------------------------------------------------------------
#define STAGE_BYTES 32768
#define NSTAGE 3
#define GEMM_SMEM_BYTES (NSTAGE * STAGE_BYTES)

__device__ __forceinline__ void load_tile_h(
    uint32_t base, const __half* __restrict__ A, const __half* __restrict__ W,
    int m0, int n0, int Kd, int k0, int tid)
{
#pragma unroll
    for (int it = 0; it < 4; it++) {
        int lin = tid + it * 256;
        int row = lin >> 3;
        int ch  = lin & 7;
        uint32_t off = (uint32_t)(row * 128 + ch * 16);
        uint32_t sw  = SWZ128(off);
        cp16(base + sw,         A + (size_t)(m0 + row) * Kd + k0 + ch * 8);
        cp16(base + 16384 + sw, W + (size_t)(n0 + row) * Kd + k0 + ch * 8);
    }
}

__global__ __launch_bounds__(256, 2) void gemm_h(
    const __half* __restrict__ A, const __half* __restrict__ W,
    const float* __restrict__ bias, const float* __restrict__ res,
    void* __restrict__ Cv, int N, int Kd, int EPI)
{
    extern __shared__ __align__(1024) char smem[];

    const int tid  = threadIdx.x;
    const int warp = tid >> 5;
    const int lane = tid & 31;
    const int gr   = lane >> 2;
    const int tig  = lane & 3;
    const int wm   = (warp & 1) * 64;
    const int wn   = (warp >> 1) * 32;
    const int m0   = blockIdx.y * 128;
    const int n0   = blockIdx.x * 128;

    const uint32_t sb = saddr(smem);

    float acc[4][4][4];
#pragma unroll
    for (int mt = 0; mt < 4; mt++)
#pragma unroll
        for (int nt = 0; nt < 4; nt++)
#pragma unroll
            for (int c = 0; c < 4; c++) acc[mt][nt][c] = 0.f;

    const int ktiles = Kd >> 6;

#pragma unroll
    for (int pf = 0; pf < NSTAGE; pf++) {
        load_tile_h(sb + pf * STAGE_BYTES, A, W, m0, n0, Kd, pf * 64, tid);
        asm volatile("cp.async.commit_group;");
    }

    for (int t = 0; t < ktiles; t++) {
        {
            int rem = ktiles - 1 - t;
            if (rem >= 2)      asm volatile("cp.async.wait_group 2;");
            else if (rem == 1) asm volatile("cp.async.wait_group 1;");
            else               asm volatile("cp.async.wait_group 0;");
        }
        __syncthreads();

        const uint32_t sA = sb + (uint32_t)((t % NSTAGE) * STAGE_BYTES);
        const uint32_t sB = sA + 16384u;

#pragma unroll
        for (int ks = 0; ks < 4; ks++) {
            uint32_t a[4][4], b[4][2];
#pragma unroll
            for (int mt = 0; mt < 4; mt++) {
                uint32_t off = (uint32_t)((wm + mt * 16 + (lane & 15)) * 128
                                          + ks * 32 + ((lane >> 4) << 4));
                ldsm4(a[mt][0], a[mt][1], a[mt][2], a[mt][3], sA + SWZ128(off));
            }
#pragma unroll
            for (int np = 0; np < 2; np++) {
                uint32_t off = (uint32_t)((wn + np * 16 + (lane & 7)
                                           + ((lane >> 4) & 1) * 8) * 128
                                          + ks * 32 + (((lane >> 3) & 1) << 4));
                ldsm4(b[2 * np][0], b[2 * np][1], b[2 * np + 1][0], b[2 * np + 1][1],
                      sB + SWZ128(off));
            }
#pragma unroll
            for (int mt = 0; mt < 4; mt++)
#pragma unroll
                for (int nt = 0; nt < 4; nt++)
                    mma_f16(acc[mt][nt][0], acc[mt][nt][1], acc[mt][nt][2], acc[mt][nt][3],
                            a[mt][0], a[mt][1], a[mt][2], a[mt][3],
                            b[nt][0], b[nt][1]);
        }
        __syncthreads();

        if (t + NSTAGE < ktiles) {
            load_tile_h(sA, A, W, m0, n0, Kd, (t + NSTAGE) * 64, tid);
            asm volatile("cp.async.commit_group;");
        }
    }

#pragma unroll
    for (int mt = 0; mt < 4; mt++) {
#pragma unroll
        for (int nt = 0; nt < 4; nt++) {
            int row = m0 + wm + mt * 16 + gr;
            int col = n0 + wn + nt * 8 + 2 * tig;
#pragma unroll
            for (int h = 0; h < 2; h++) {
                int r = row + h * 8;
                float c0 = acc[mt][nt][h * 2 + 0];
                float c1 = acc[mt][nt][h * 2 + 1];
                if (EPI == 0) {
                    *(__half2*)((__half*)Cv + (size_t)r * N + col) =
                        __floats2half2_rn(c0, c1);
                } else if (EPI == 1) {
                    c0 = fmaxf(c0 + bias[col], 0.f);
                    c1 = fmaxf(c1 + bias[col + 1], 0.f);
                    *(__half2*)((__half*)Cv + (size_t)r * N + col) =
                        __floats2half2_rn(c0, c1);
                } else if (EPI == 2) {
                    const float2 rv = *(const float2*)(res + (size_t)r * N + col);
                    float2 o; o.x = c0 + bias[col] + rv.x; o.y = c1 + bias[col + 1] + rv.y;
                    *(float2*)((float*)Cv + (size_t)r * N + col) = o;
                } else {
                    const float2 rv = *(const float2*)(res + (size_t)r * N + col);
                    float2 o; o.x = c0 + rv.x; o.y = c1 + rv.y;
                    *(float2*)((float*)Cv + (size_t)r * N + col) = o;
                }
            }
        }
    }
}

// ---------------------------------------------------------------------------
// f32 -> fp16 converters
// ---------------------------------------------------------------------------
__global__ __launch_bounds__(256) void cvt_h(
    const float* __restrict__ in, __half* __restrict__ out)
{
    int i = blockIdx.x * blockDim.x + threadIdx.x;
    float4 v = ((const float4*)in)[i];
    ((__half2*)out)[2 * i]     = __floats2half2_rn(v.x, v.y);
    ((__half2*)out)[2 * i + 1] = __floats2half2_rn(v.z, v.w);
}

__global__ __launch_bounds__(256) void pack_qkv_h(
    const float* __restrict__ Wq, const float* __restrict__ Wk,
    const float* __restrict__ Wv, __half* __restrict__ Wp)
{
    int i = blockIdx.x * blockDim.x + threadIdx.x;
    int row = (i * 4) >> 10;
    int col = (i * 4) & 1023;
    const float* src;
    if (row < 1024)      src = Wq + (size_t)row * 1024 + col;
    else if (row < 2048) src = Wk + (size_t)(row - 1024) * 1024 + col;
    else                 src = Wv + (size_t)(row - 2048) * 1024 + col;
    float4 v = *(const float4*)src;
    ((__half2*)Wp)[2 * i]     = __floats2half2_rn(v.x, v.y);
    ((__half2*)Wp)[2 * i + 1] = __floats2half2_rn(v.z, v.w);
}

// ---------------------------------------------------------------------------
// FA2-style fp16 flash attention on packed qkv [8192, 3072].
// Block = 128 q-rows of one head; 8 warps, each warp owns 16 q-rows x all
// 64 t-cols -> softmax entirely in registers (xor-shuffles in row groups).
// Q fragments loaded to registers once. K/V: 2-stage cp.async pipeline.
// S D-frags repack directly into PV A-frags (no P smem).
// ---------------------------------------------------------------------------
#define BQ 128
#define HSTR 72                          // padded row: 72 halves = 144 B
#define Q_BYTES   (BQ * 144)             // 18432
#define KV_STAGE  (2 * 64 * 144)         // K + V per stage = 18432
#define ATTN_SMEM (Q_BYTES + 2 * KV_STAGE)   // 55296
#define QKV_SSTRIDE (4*3072)

__global__ __launch_bounds__(256, 2) void attn_reg(
    const __half* __restrict__ qkv, const float* __restrict__ mask,
    __half* __restrict__ u)
{
    extern __shared__ __align__(1024) char smc[];
    __half* Qh = (__half*)smc;

    const int n   = blockIdx.y;          // head (b*16+h)
    const int bb  = n >> 4;
    const int hh  = n & 15;
    const int s0  = blockIdx.x * BQ;
    const int tid = threadIdx.x;
    const int warp = tid >> 5;
    const int lane = tid & 31;
    const int gr   = lane >> 2;
    const int tig  = lane & 3;
    const int wq   = warp * 16;          // warp's q-row base within tile

    const uint32_t sQ  = saddr(smc);
    const uint32_t sKV = sQ + Q_BYTES;

    const __half* qb = qkv + (size_t)bb * 3072 + hh * 64;
    const __half* kb = qb + 1024;
    const __half* vb = qb + 2048;

    // ---- load Q tile (128 x 64 halves) to smem ----
#pragma unroll
    for (int it = 0; it < 4; it++) {
        int lin = tid + it * 256;        // 0..1023
        int row = lin >> 3;
        int ch  = (lin & 7) * 8;
        uint4 v = *(const uint4*)(qb + (size_t)(s0 + row) * QKV_SSTRIDE + ch);
        *(uint4*)(Qh + row * HSTR + ch) = v;
    }
    __syncthreads();

    // ---- Q fragments to registers (4 k-tiles) ----
    uint32_t qf[4][4];
#pragma unroll
    for (int ks = 0; ks < 4; ks++) {
        uint32_t off = (uint32_t)((wq + (lane & 15)) * 144
                                  + ks * 32 + ((lane >> 4) << 4));
        ldsm4(qf[ks][0], qf[ks][1], qf[ks][2], qf[ks][3], sQ + off);
    }
    __syncthreads();

    // ---- prefetch K/V tile 0 into stage 0 ----
    {
#pragma unroll
        for (int it = 0; it < 4; it++) {
            int lin = tid + it * 256;            // 0..1023
            int row = (lin >> 3) & 63;
            int sel = lin >> 9;                  // 0=K 1=V
            int ch  = lin & 7;
            const __half* src = (sel ? vb : kb) + (size_t)row * QKV_SSTRIDE + ch * 8;
            cp16(sKV + (uint32_t)(sel * 9216 + row * 144 + ch * 16), src);
        }
        asm volatile("cp.async.commit_group;");
    }

    float oacc[8][4];
#pragma unroll
    for (int nt = 0; nt < 8; nt++)
#pragma unroll
        for (int c = 0; c < 4; c++) oacc[nt][c] = 0.f;
    float m0r = -1e30f, m1r = -1e30f;    // running max rows (wq+gr), (wq+gr+8)
    float l0r = 0.f,    l1r = 0.f;       // running denom

    const int NT = SEQ / 64;             // 32 t-tiles

    for (int t = 0; t < NT; t++) {
        asm volatile("cp.async.wait_group 0;");
        __syncthreads();

        const uint32_t sK = sKV + (uint32_t)((t & 1) * KV_STAGE);
        const uint32_t sV = sK + 9216u;

        // prefetch next tile into the other stage
        if (t + 1 < NT) {
            const int t0n = (t + 1) * 64;
            const uint32_t dst = sKV + (uint32_t)(((t + 1) & 1) * KV_STAGE);
#pragma unroll
            for (int it = 0; it < 4; it++) {
                int lin = tid + it * 256;
                int row = (lin >> 3) & 63;
                int sel = lin >> 9;
                int ch  = lin & 7;
                const __half* src = (sel ? vb : kb)
                    + (size_t)(t0n + row) * QKV_SSTRIDE + ch * 8;
                cp16(dst + (uint32_t)(sel * 9216 + row * 144 + ch * 16), src);
            }
            asm volatile("cp.async.commit_group;");
        }

        // ---- S = Q K^T : 8 n-tiles (64 t-cols) ----
        float sacc[8][4];
#pragma unroll
        for (int nt = 0; nt < 8; nt++)
#pragma unroll
            for (int c = 0; c < 4; c++) sacc[nt][c] = 0.f;
#pragma unroll
        for (int ks = 0; ks < 4; ks++) {
#pragma unroll
            for (int np = 0; np < 4; np++) {
                uint32_t b0, b1, b2, b3;
                uint32_t off = (uint32_t)((np * 16 + (lane & 7)
                                           + ((lane >> 4) & 1) * 8) * 144
                                          + ks * 32 + (((lane >> 3) & 1) << 4));
                ldsm4(b0, b1, b2, b3, sK + off);
                mma_f16(sacc[2*np][0], sacc[2*np][1], sacc[2*np][2], sacc[2*np][3],
                        qf[ks][0], qf[ks][1], qf[ks][2], qf[ks][3], b0, b1);
                mma_f16(sacc[2*np+1][0], sacc[2*np+1][1], sacc[2*np+1][2], sacc[2*np+1][3],
                        qf[ks][0], qf[ks][1], qf[ks][2], qf[ks][3], b2, b3);
            }
        }

        // ---- mask (BEFORE scale) + scale, in registers ----
        const int t0 = t * 64;
        const int r0g = s0 + wq + gr;
#pragma unroll
        for (int nt = 0; nt < 8; nt++) {
            int col = t0 + nt * 8 + 2 * tig;
            const float2 mv0 = *(const float2*)(mask + (size_t)r0g * SEQ + col);
            const float2 mv1 = *(const float2*)(mask + (size_t)(r0g + 8) * SEQ + col);
            sacc[nt][0] = (sacc[nt][0] + mv0.x) * 0.125f;
            sacc[nt][1] = (sacc[nt][1] + mv0.y) * 0.125f;
            sacc[nt][2] = (sacc[nt][2] + mv1.x) * 0.125f;
            sacc[nt][3] = (sacc[nt][3] + mv1.y) * 0.125f;
        }

        // ---- row max via xor-shuffles (4 threads per row) ----
        float tm0 = -1e30f, tm1 = -1e30f;
#pragma unroll
        for (int nt = 0; nt < 8; nt++) {
            tm0 = fmaxf(tm0, fmaxf(sacc[nt][0], sacc[nt][1]));
            tm1 = fmaxf(tm1, fmaxf(sacc[nt][2], sacc[nt][3]));
        }
        tm0 = fmaxf(tm0, __shfl_xor_sync(0xffffffffu, tm0, 1));
        tm0 = fmaxf(tm0, __shfl_xor_sync(0xffffffffu, tm0, 2));
        tm1 = fmaxf(tm1, __shfl_xor_sync(0xffffffffu, tm1, 1));
        tm1 = fmaxf(tm1, __shfl_xor_sync(0xffffffffu, tm1, 2));

        float nm0 = fmaxf(m0r, tm0);
        float nm1 = fmaxf(m1r, tm1);
        float cr0 = __expf(m0r - nm0);
        float cr1 = __expf(m1r - nm1);
        m0r = nm0; m1r = nm1;

        // ---- exp + pack P into A-fragments; accumulate row sums ----
        uint32_t pf[4][4];
        float sum0 = 0.f, sum1 = 0.f;
#pragma unroll
        for (int j = 0; j < 4; j++) {           // k-tile j = score tiles 2j,2j+1
            float e00 = __expf(sacc[2*j][0] - nm0);
            float e01 = __expf(sacc[2*j][1] - nm0);
            float e02 = __expf(sacc[2*j][2] - nm1);
            float e03 = __expf(sacc[2*j][3] - nm1);
            float e10 = __expf(sacc[2*j+1][0] - nm0);
            float e11 = __expf(sacc[2*j+1][1] - nm0);
            float e12 = __expf(sacc[2*j+1][2] - nm1);
            float e13 = __expf(sacc[2*j+1][3] - nm1);
            sum0 += e00 + e01 + e10 + e11;
            sum1 += e02 + e03 + e12 + e13;
            pf[j][0] = h2u(__floats2half2_rn(e00, e01));
            pf[j][1] = h2u(__floats2half2_rn(e02, e03));
            pf[j][2] = h2u(__floats2half2_rn(e10, e11));
            pf[j][3] = h2u(__floats2half2_rn(e12, e13));
        }
        sum0 += __shfl_xor_sync(0xffffffffu, sum0, 1);
        sum0 += __shfl_xor_sync(0xffffffffu, sum0, 2);
        sum1 += __shfl_xor_sync(0xffffffffu, sum1, 1);
        sum1 += __shfl_xor_sync(0xffffffffu, sum1, 2);
        l0r = l0r * cr0 + sum0;
        l1r = l1r * cr1 + sum1;

        // ---- rescale O, then O += P @ V (V^T frags via ldmatrix.trans) ----
#pragma unroll
        for (int nt = 0; nt < 8; nt++) {
            oacc[nt][0] *= cr0; oacc[nt][1] *= cr0;
            oacc[nt][2] *= cr1; oacc[nt][3] *= cr1;
        }
#pragma unroll
        for (int ks = 0; ks < 4; ks++) {
#pragma unroll
            for (int np = 0; np < 4; np++) {
                uint32_t b0, b1, b2, b3;
                int vrow = ks * 16 + (lane & 7) + ((lane >> 3) & 1) * 8;
                int vcol = np * 16 + ((lane >> 4) & 1) * 8;
                ldsm4_t(b0, b1, b2, b3, sV + (uint32_t)(vrow * 144 + vcol * 2));
                mma_f16(oacc[2*np][0], oacc[2*np][1], oacc[2*np][2], oacc[2*np][3],
                        pf[ks][0], pf[ks][1], pf[ks][2], pf[ks][3], b0, b1);
                mma_f16(oacc[2*np+1][0], oacc[2*np+1][1], oacc[2*np+1][2], oacc[2*np+1][3],
                        pf[ks][0], pf[ks][1], pf[ks][2], pf[ks][3], b2, b3);
            }
        }
    }

    // ---- final normalize + store fp16 ----
    {
        float inv0 = 1.f / l0r;
        float inv1 = 1.f / l1r;
        const int r0g = s0 + wq + gr;
#pragma unroll
        for (int nt = 0; nt < 8; nt++) {
            int col = nt * 8 + 2 * tig;
            *(__half2*)(u + (size_t)r0g * 4096 + (size_t)n * 64 + col) =
                __floats2half2_rn(oacc[nt][0] * inv0, oacc[nt][1] * inv0);
            *(__half2*)(u + (size_t)(r0g + 8) * 4096 + (size_t)n * 64 + col) =
                __floats2half2_rn(oacc[nt][2] * inv1, oacc[nt][3] * inv1);
        }
    }
}

// ---------------------------------------------------------------------------
// LayerNorm over last dim (1024); optional fp16 secondary output.
// ---------------------------------------------------------------------------
__global__ __launch_bounds__(256) void ln_kernel(
    const float* __restrict__ in, const float* __restrict__ g,
    const float* __restrict__ be, float* __restrict__ out,
    __half* __restrict__ outh)
{
    const int row = blockIdx.x;
    const int tid = threadIdx.x;
    __shared__ float red[8];
    __shared__ float s_mu, s_rstd;

    float4 v = *(const float4*)(in + (size_t)row * DMODEL + tid * 4);
    float s = v.x + v.y + v.z + v.w;
#pragma unroll
    for (int o = 16; o > 0; o >>= 1) s += __shfl_xor_sync(0xffffffffu, s, o);
    if ((tid & 31) == 0) red[tid >> 5] = s;
    __syncthreads();
    if (tid < 8) {
        float t = red[tid];
#pragma unroll
        for (int o = 4; o > 0; o >>= 1) t += __shfl_xor_sync(0xffu, t, o);
        if (tid == 0) s_mu = t * (1.f / DMODEL);
    }
    __syncthreads();
    float mu = s_mu;
    float d0 = v.x - mu, d1 = v.y - mu, d2 = v.z - mu, d3 = v.w - mu;
    float s2 = d0 * d0 + d1 * d1 + d2 * d2 + d3 * d3;
#pragma unroll
    for (int o = 16; o > 0; o >>= 1) s2 += __shfl_xor_sync(0xffffffffu, s2, o);
    if ((tid & 31) == 0) red[tid >> 5] = s2;
    __syncthreads();
    if (tid < 8) {
        float t = red[tid];
#pragma unroll
        for (int o = 4; o > 0; o >>= 1) t += __shfl_xor_sync(0xffu, t, o);
        if (tid == 0) s_rstd = rsqrtf(t * (1.f / DMODEL) + LN_EPS);
    }
    __syncthreads();
    float rstd = s_rstd;
    float4 gv = *(const float4*)(g + tid * 4);
    float4 bv = *(const float4*)(be + tid * 4);
    float4 ov;
    ov.x = d0 * rstd * gv.x + bv.x;
    ov.y = d1 * rstd * gv.y + bv.y;
    ov.z = d2 * rstd * gv.z + bv.z;
    ov.w = d3 * rstd * gv.w + bv.w;
    *(float4*)(out + (size_t)row * DMODEL + tid * 4) = ov;
    if (outh != nullptr) {
        *(__half2*)(outh + (size_t)row * DMODEL + tid * 4)     = __floats2half2_rn(ov.x, ov.y);
        *(__half2*)(outh + (size_t)row * DMODEL + tid * 4 + 2) = __floats2half2_rn(ov.z, ov.w);
    }
}

// ---------------------------------------------------------------------------
extern "C" void kernel_launch(void* const* d_in, const int* in_sizes, int n_in,
                              void* d_out, int out_size)
{
    const float* x    = (const float*)d_in[0];
    const float* mask = (const float*)d_in[1];
    const float* Wq   = (const float*)d_in[2];
    const float* Wk   = (const float*)d_in[3];
    const float* Wv   = (const float*)d_in[4];
    const float* Wc   = (const float*)d_in[5];
    const float* W1   = (const float*)d_in[6];
    const float* b1   = (const float*)d_in[7];
    const float* W2   = (const float*)d_in[8];
    const float* b2   = (const float*)d_in[9];
    const float* g1   = (const float*)d_in[10];
    const float* be1  = (const float*)d_in[11];
    const float* g2   = (const float*)d_in[12];
    const float* be2  = (const float*)d_in[13];
    float* out = (float*)d_out;

    __half *xh, *wph, *wch, *w1h, *w2h, *qkvh, *uh, *t2h, *hidh;
    float *t1, *t2, *t3;
    cudaGetSymbolAddress((void**)&xh,   g_xh);
    cudaGetSymbolAddress((void**)&wph,  g_wph);
    cudaGetSymbolAddress((void**)&wch,  g_wch);
    cudaGetSymbolAddress((void**)&w1h,  g_w1h);
    cudaGetSymbolAddress((void**)&w2h,  g_w2h);
    cudaGetSymbolAddress((void**)&qkvh, g_qkvh);
    cudaGetSymbolAddress((void**)&uh,   g_uh);
    cudaGetSymbolAddress((void**)&t2h,  g_t2h);
    cudaGetSymbolAddress((void**)&hidh, g_hidh);
    cudaGetSymbolAddress((void**)&t1,   g_t1);
    cudaGetSymbolAddress((void**)&t2,   g_t2);
    cudaGetSymbolAddress((void**)&t3,   g_t3);

    cudaFuncSetAttribute(attn_reg, cudaFuncAttributeMaxDynamicSharedMemorySize, ATTN_SMEM);
    cudaFuncSetAttribute(gemm_h, cudaFuncAttributeMaxDynamicSharedMemorySize, GEMM_SMEM_BYTES);

    dim3 blk(256);

    // fp16 conversions
    cvt_h<<<(MROWS * DMODEL / 4) / 256, blk>>>(x, xh);
    pack_qkv_h<<<(3072 * DMODEL / 4) / 256, blk>>>(Wq, Wk, Wv, wph);
    cvt_h<<<(DMODEL * DMODEL / 4) / 256, blk>>>(Wc, wch);
    cvt_h<<<(FFDIM * DMODEL / 4) / 256, blk>>>(W1, w1h);
    cvt_h<<<(DMODEL * FFDIM / 4) / 256, blk>>>(W2, w2h);

    // fused QKV projection -> qkvh fp16 [8192, 3072]
    gemm_h<<<dim3(3072 / 128, MROWS / 128), blk, GEMM_SMEM_BYTES>>>(
        xh, wph, nullptr, nullptr, qkvh, 3072, DMODEL, 0);

    // attention -> uh fp16
    attn_reg<<<dim3(SEQ / BQ, 64), blk, ATTN_SMEM>>>(qkvh, mask, uh);

    // x + u @ Wc^T -> t1 f32;  LN1 -> t2 f32 + t2h fp16
    gemm_h<<<dim3(DMODEL / 128, MROWS / 128), blk, GEMM_SMEM_BYTES>>>(
        uh, wch, nullptr, x, t1, DMODEL, DMODEL, 3);
    ln_kernel<<<MROWS, blk>>>(t1, g1, be1, t2, t2h);

    // FFN: relu(t2@W1^T+b1) -> hidh;  hid@W2^T+b2 + t2 -> t3;  LN2 -> out
    gemm_h<<<dim3(FFDIM / 128, MROWS / 128), blk, GEMM_SMEM_BYTES>>>(
        t2h, w1h, b1, nullptr, hidh, FFDIM, DMODEL, 1);
    gemm_h<<<dim3(DMODEL / 128, MROWS / 128), blk, GEMM_SMEM_BYTES>>>(
        hidh, w2h, b2, t2, t3, DMODEL, FFDIM, 2);
    ln_kernel<<<MROWS, blk>>>(t3, g2, be2, out, nullptr);
}